// round 12
// baseline (speedup 1.0000x reference)
#include <cuda_runtime.h>
#include <cuda_fp16.h>
#include <cstdint>
#include <cstddef>

// Problem constants
constexpr int HIDC  = 1024;
constexpr int SEQ   = 1024;
constexpr int NBAT  = 2;
constexpr int CACHE = 3072;
constexpr int TKV   = 4096;
constexpr int MTOT  = NBAT * SEQ;               // 2048 rows
constexpr size_t PLANE = (size_t)MTOT * HIDC;   // 2,097,152

// Output offsets (floats)
constexpr size_t OFF_OUT_RE = 0;
constexpr size_t OFF_OUT_IM = 2097152;
constexpr size_t OFF_K_RE   = 4194304;
constexpr size_t OFF_K_IM   = 12582912;
constexpr size_t OFF_V_RE   = 20971520;
constexpr size_t OFF_V_IM   = 29360128;

// Scratch (device globals — allocation-free)
__device__ __half g_nrh[PLANE];                  // LN out (fp16, perm16 over k)
__device__ __half g_nih[PLANE];
__device__ __half g_arh[PLANE];                  // attn out (fp16, perm16 over hid)
__device__ __half g_aih[PLANE];
__device__ __half g_qh[(size_t)32 * 1024 * 128]; // Q plane [bh][tok][128] perm16
__device__ __half g_kh[(size_t)32 * 4096 * 128]; // K plane [bh][tok][128] perm16
__device__ __half g_vt[(size_t)32 * 128 * 4096]; // V^T plane [bh][dim][tok]
__device__ __half g_wh[(size_t)8 * 1024 * 1024]; // weights fp16 perm16

// ---------------- helpers ----------------
__device__ __forceinline__ unsigned u32(float x) { return __float_as_uint(x); }

// perm16: reorder each 16-element k-group so a thread's fp16 fragment
// (k = {2t4, 2t4+1, 2t4+8, 2t4+9}) is 4 contiguous halves.
__device__ __forceinline__ int slot16(int w) {
    return ((w >> 1) & 3) * 4 + ((w >> 3) & 1) * 2 + (w & 1);
}
__device__ __forceinline__ int permidx(int k) { return (k & ~15) + slot16(k & 15); }

__device__ __forceinline__ unsigned packh2(float x, float y) {
    __half2 h = __floats2half2_rn(x, y);
    return *reinterpret_cast<unsigned*>(&h);
}

__device__ __forceinline__ void mmaf16(float* c, unsigned a0, unsigned a1, unsigned a2,
                                       unsigned a3, unsigned b0, unsigned b1) {
    asm("mma.sync.aligned.m16n8k16.row.col.f32.f16.f16.f32 "
        "{%0,%1,%2,%3},{%4,%5,%6,%7},{%8,%9},{%0,%1,%2,%3};"
        : "+f"(c[0]), "+f"(c[1]), "+f"(c[2]), "+f"(c[3])
        : "r"(a0), "r"(a1), "r"(a2), "r"(a3), "r"(b0), "r"(b1));
}

__device__ __forceinline__ void cpa16(unsigned dst, const void* src) {
    asm volatile("cp.async.cg.shared.global [%0], [%1], 16;" :: "r"(dst), "l"(src) : "memory");
}
__device__ __forceinline__ void cpcommit() { asm volatile("cp.async.commit_group;" ::: "memory"); }
__device__ __forceinline__ void cpwait1() { asm volatile("cp.async.wait_group 1;" ::: "memory"); }
__device__ __forceinline__ void cpwait0() { asm volatile("cp.async.wait_group 0;" ::: "memory"); }

// ---------------- weight convert: fp32 -> fp16 perm16 (sector-coalesced) ----------------
__global__ void wconv_kernel(const float* s0, const float* s1, const float* s2, const float* s3,
                             const float* s4, const float* s5, const float* s6, const float* s7,
                             __half* dst) {
    size_t i = (size_t)blockIdx.x * blockDim.x + threadIdx.x;   // 8M threads
    int p = (int)(i >> 20);
    size_t w = i & 1048575u;
    const float* sp;
    switch (p) {
        case 0: sp = s0; break; case 1: sp = s1; break;
        case 2: sp = s2; break; case 3: sp = s3; break;
        case 4: sp = s4; break; case 5: sp = s5; break;
        case 6: sp = s6; break; default: sp = s7; break;
    }
    int k = (int)(w & 1023);
    dst[(i & ~(size_t)1023) + permidx(k)] = __float2half(sp[w]);
}

// ---------------- K cache convert: fp32 [b][t][h][64] -> K plane (perm16) ----------------
__global__ void kcache_conv(const float* __restrict__ re, const float* __restrict__ im,
                            __half* __restrict__ Kh) {
    size_t i = (size_t)blockIdx.x * blockDim.x + threadIdx.x;   // 2*3072*1024
    int hd = (int)(i & 1023);
    int t  = (int)((i >> 10) % 3072u);
    int b  = (int)(i / (3072u * 1024u));
    int h = hd >> 6, d = hd & 63;
    size_t base = ((size_t)(b * 16 + h) * 4096 + t) * 128;
    int s = (d & ~15) + slot16(d & 15);
    Kh[base + s]      = __float2half(re[i]);
    Kh[base + 64 + s] = __float2half(im[i]);
}

// ---------------- V transpose: fp32 V [b][tok 4096][hid] -> fp16 V^T [bh][dim 128][tok] ----------------
__global__ void vtrans_kernel(const float* __restrict__ Vr, const float* __restrict__ Vi,
                              __half* __restrict__ Vt) {
    __shared__ float Tr[64][65];
    __shared__ float Ti[64][65];
    int tt = blockIdx.x;            // token tile 0..63
    int bh = blockIdx.y;            // 0..31
    int b = bh >> 4, h = bh & 15;
    int t0 = tt * 64;
    int tid = threadIdx.x;
#pragma unroll
    for (int i = 0; i < 16; i++) {
        int id = tid + i * 256;
        int tok = id >> 6, d = id & 63;
        size_t src = ((size_t)b * TKV + t0 + tok) * HIDC + h * 64 + d;
        Tr[tok][d] = Vr[src];
        Ti[tok][d] = Vi[src];
    }
    __syncthreads();
#pragma unroll
    for (int i = 0; i < 32; i++) {
        int id = tid + i * 256;
        int dim = id >> 6, tok = id & 63;
        float v = (dim < 64) ? Tr[tok][dim] : Ti[tok][dim - 64];
        Vt[((size_t)bh * 128 + dim) * 4096 + t0 + tok] = __float2half(v);
    }
}

// ---------------- Complex LayerNorm -> fp16 perm16 planes ----------------
__global__ void ln_kernel(const float* __restrict__ hr, const float* __restrict__ hi,
                          const float* __restrict__ gamma,
                          const float* __restrict__ betar, const float* __restrict__ betai,
                          __half* __restrict__ nr, __half* __restrict__ ni) {
    int row = blockIdx.x;
    int tid = threadIdx.x, lane = tid & 31, wid = tid >> 5;
    const float* pr = hr + (size_t)row * HIDC;
    const float* pi = hi + (size_t)row * HIDC;

    float vr[4], vi[4];
    float sr = 0.f, si = 0.f, sq = 0.f;
#pragma unroll
    for (int j = 0; j < 4; j++) {
        int e = tid + j * 256;
        vr[j] = pr[e]; vi[j] = pi[e];
        sr += vr[j]; si += vi[j]; sq += vr[j] * vr[j] + vi[j] * vi[j];
    }
#pragma unroll
    for (int o = 16; o; o >>= 1) {
        sr += __shfl_xor_sync(0xffffffffu, sr, o);
        si += __shfl_xor_sync(0xffffffffu, si, o);
        sq += __shfl_xor_sync(0xffffffffu, sq, o);
    }
    __shared__ float red[3][8];
    if (lane == 0) { red[0][wid] = sr; red[1][wid] = si; red[2][wid] = sq; }
    __syncthreads();
    float tsr = 0.f, tsi = 0.f, tsq = 0.f;
#pragma unroll
    for (int w = 0; w < 8; w++) { tsr += red[0][w]; tsi += red[1][w]; tsq += red[2][w]; }
    float mur = tsr * (1.0f / HIDC);
    float mui = tsi * (1.0f / HIDC);
    float var = tsq * (1.0f / HIDC) - mur * mur - mui * mui;
    float inv = rsqrtf(var + 1e-5f);
#pragma unroll
    for (int j = 0; j < 4; j++) {
        int e = tid + j * 256;
        float gm = gamma[e] * inv;
        int pe = permidx(e);
        nr[(size_t)row * HIDC + pe] = __float2half((vr[j] - mur) * gm + betar[e]);
        ni[(size_t)row * HIDC + pe] = __float2half((vi[j] - mui) * gm + betai[e]);
    }
}

// ---------------- Complex projection GEMM (fp16 mma) ----------------
// MODE 0=Q (fp16 Q plane), 1=K (fp32 kv + fp16 K plane), 2=V (fp32 kv), 3=O (fp32 + resid)
constexpr int PA_S = 40;                  // row stride in halves (80 B)
constexpr int PASZ = 128 * PA_S;          // 5120 halves
constexpr int PBSZ = 64 * PA_S;           // 2560 halves

template <int MODE>
__global__ void __launch_bounds__(256, 2)
proj_kernel(const __half* __restrict__ A1, const __half* __restrict__ A2,
            const __half* __restrict__ Wr, const __half* __restrict__ Wi,
            const float* __restrict__ brp, const float* __restrict__ bip,
            float* __restrict__ Or, float* __restrict__ Oi,
            __half* __restrict__ Hout,
            const float* __restrict__ Rr, const float* __restrict__ Ri) {
    __shared__ __half sm[2 * PASZ + 4 * PBSZ];   // 40960 B -> occ 2
    unsigned sbase = (unsigned)__cvta_generic_to_shared(sm);

    int tid = threadIdx.x, lane = tid & 31, wid = tid >> 5;
    int wm = wid & 3, wn = wid >> 2;
    int g = lane >> 2, t4 = lane & 3;
    int n0 = blockIdx.x * 64;
    int m0 = blockIdx.y * 128;

    float accR[2][4][4];
    float accI[2][4][4];
#pragma unroll
    for (int a = 0; a < 2; a++)
#pragma unroll
        for (int b = 0; b < 4; b++)
#pragma unroll
            for (int c = 0; c < 4; c++) { accR[a][b][c] = 0.f; accI[a][b][c] = 0.f; }

    auto issue = [&](int it) {
        bool ph2 = it >= 32;
        int ko = it * 32 - (ph2 ? 1024 : 0);
        const __half* Ap = ph2 ? A2 : A1;
        int buf = it & 1;
#pragma unroll
        for (int i = 0; i < 2; i++) {
            int id = tid + i * 256;
            int r = id >> 2, c = id & 3;
            cpa16(sbase + (unsigned)(buf * PASZ + r * PA_S) * 2u + c * 16,
                  Ap + (size_t)(m0 + r) * HIDC + ko + c * 8);
        }
#pragma unroll
        for (int i = 0; i < 2; i++) {
            int id = tid + i * 256;
            int pl = id >> 8, r = (id >> 2) & 63, c = id & 3;
            const __half* Wp = pl ? Wi : Wr;
            unsigned off = 2 * PASZ + (pl * 2 + buf) * PBSZ;
            cpa16(sbase + (off + (unsigned)(r * PA_S)) * 2u + c * 16,
                  Wp + (size_t)(n0 + r) * HIDC + ko + c * 8);
        }
        cpcommit();
    };

    issue(0);
    issue(1);

    for (int it = 0; it < 64; it++) {
        if (it < 63) cpwait1(); else cpwait0();
        __syncthreads();

        int buf = it & 1;
        bool ph2 = (it >= 32);
        const __half* Ab = sm + buf * PASZ;
        const __half* Bb = sm + 2 * PASZ + buf * PBSZ;

#pragma unroll
        for (int ks = 0; ks < 2; ks++) {
            unsigned af[2][4];
#pragma unroll
            for (int mt = 0; mt < 2; mt++) {
                const __half* ap = Ab + (wm * 32 + mt * 16 + g) * PA_S + ks * 16 + t4 * 4;
                uint2 lo = *reinterpret_cast<const uint2*>(ap);
                uint2 hi = *reinterpret_cast<const uint2*>(ap + 8 * PA_S);
                af[mt][0] = lo.x; af[mt][1] = hi.x; af[mt][2] = lo.y; af[mt][3] = hi.y;
            }
            unsigned naf[2][4];
            if (ph2) {
#pragma unroll
                for (int mt = 0; mt < 2; mt++)
#pragma unroll
                    for (int q = 0; q < 4; q++) naf[mt][q] = af[mt][q] ^ 0x80008000u;
            }
#pragma unroll
            for (int nt = 0; nt < 4; nt++) {
                const __half* bp = Bb + (wn * 32 + nt * 8 + g) * PA_S + ks * 16 + t4 * 4;
                uint2 bR = *reinterpret_cast<const uint2*>(bp);
                uint2 bI = *reinterpret_cast<const uint2*>(bp + 2 * PBSZ);
                if (ph2) {
#pragma unroll
                    for (int mt = 0; mt < 2; mt++) {
                        mmaf16(accR[mt][nt], naf[mt][0], naf[mt][1], naf[mt][2], naf[mt][3], bI.x, bI.y);
                        mmaf16(accI[mt][nt], af[mt][0], af[mt][1], af[mt][2], af[mt][3], bR.x, bR.y);
                    }
                } else {
#pragma unroll
                    for (int mt = 0; mt < 2; mt++) {
                        mmaf16(accR[mt][nt], af[mt][0], af[mt][1], af[mt][2], af[mt][3], bR.x, bR.y);
                        mmaf16(accI[mt][nt], af[mt][0], af[mt][1], af[mt][2], af[mt][3], bI.x, bI.y);
                    }
                }
            }
        }
        __syncthreads();
        if (it + 2 < 64) issue(it + 2);
    }

    // epilogue
#pragma unroll
    for (int mt = 0; mt < 2; mt++) {
#pragma unroll
        for (int hrw = 0; hrw < 2; hrw++) {
            int r = m0 + wm * 32 + mt * 16 + g + hrw * 8;
            int bq = r >> 10, tk = r & 1023;
#pragma unroll
            for (int nt = 0; nt < 4; nt++) {
                int c0 = n0 + wn * 32 + nt * 8 + 2 * t4;
                float vr0 = accR[mt][nt][hrw * 2 + 0] + brp[c0];
                float vr1 = accR[mt][nt][hrw * 2 + 1] + brp[c0 + 1];
                float vi0 = accI[mt][nt][hrw * 2 + 0] + bip[c0];
                float vi1 = accI[mt][nt][hrw * 2 + 1] + bip[c0 + 1];
                int h = c0 >> 6, d = c0 & 63;
                int s = (d & ~15) + slot16(d & 15);

                if (MODE == 0) {
                    size_t base = ((size_t)(bq * 16 + h) * 1024 + tk) * 128;
                    *reinterpret_cast<__half2*>(Hout + base + s) = __floats2half2_rn(vr0, vr1);
                    *reinterpret_cast<__half2*>(Hout + base + 64 + s) = __floats2half2_rn(vi0, vi1);
                } else if (MODE == 1) {
                    size_t orow = (size_t)bq * TKV + CACHE + tk;
                    Or[orow * HIDC + c0] = vr0;  Or[orow * HIDC + c0 + 1] = vr1;
                    Oi[orow * HIDC + c0] = vi0;  Oi[orow * HIDC + c0 + 1] = vi1;
                    size_t base = ((size_t)(bq * 16 + h) * 4096 + CACHE + tk) * 128;
                    *reinterpret_cast<__half2*>(Hout + base + s) = __floats2half2_rn(vr0, vr1);
                    *reinterpret_cast<__half2*>(Hout + base + 64 + s) = __floats2half2_rn(vi0, vi1);
                } else if (MODE == 2) {
                    size_t orow = (size_t)bq * TKV + CACHE + tk;
                    Or[orow * HIDC + c0] = vr0;  Or[orow * HIDC + c0 + 1] = vr1;
                    Oi[orow * HIDC + c0] = vi0;  Oi[orow * HIDC + c0 + 1] = vi1;
                } else {
                    size_t rowo = (size_t)r * HIDC;
                    Or[rowo + c0]     = vr0 + Rr[rowo + c0];
                    Or[rowo + c0 + 1] = vr1 + Rr[rowo + c0 + 1];
                    Oi[rowo + c0]     = vi0 + Ri[rowo + c0];
                    Oi[rowo + c0 + 1] = vi1 + Ri[rowo + c0 + 1];
                }
            }
        }
    }
}

// ---------------- Flash attention (fp16 mma, fused balanced pair, 512 threads) ----------------
// grid 128: CTA c -> bh = c>>2, p = c&3. Warps 0-7 own q-block p (rows 0-127 of Qs),
// warps 8-15 own q-block 7-p (rows 128-255). K/V tiles shared by both halves.
constexpr int AQ_S = 136;                 // halves
constexpr int AK_S = 136;
constexpr int AV_S = 72;                  // V^T rows (64 kv + 8 pad)
constexpr int Q_SZ = 256 * AQ_S;          // 34816 halves (256 q rows)
constexpr int K_SZ = 64 * AK_S;           // 8704
constexpr int V_SZ = 128 * AV_S;          // 9216
constexpr int AT_SMEM = (Q_SZ + 2 * K_SZ + 2 * V_SZ) * 2;   // 141312 bytes

__global__ void __launch_bounds__(512, 1)
attn_kernel(const __half* __restrict__ Qp, const __half* __restrict__ Kp,
            const __half* __restrict__ Vp,
            __half* __restrict__ ar, __half* __restrict__ ai) {
    extern __shared__ __half smh[];
    __half* Qs = smh;
    unsigned sbase = (unsigned)__cvta_generic_to_shared(smh);

    int tid = threadIdx.x, lane = tid & 31, wid = tid >> 5;   // wid 0..15
    int g = lane >> 2, t4 = lane & 3;
    int bh = blockIdx.x >> 2;
    int p  = blockIdx.x & 3;
    int b = bh >> 4, h = bh & 15;

    int wg  = wid >> 3;                         // 0 = lower pair member, 1 = upper
    int qb  = wg ? (7 - p) : p;
    int q0  = qb * 128;                         // this warp's q-block base
    int wq  = wg * 128 + (wid & 7) * 16;        // row base within Qs

    int q0max   = (7 - p) * 128;                // p in 0..3 -> 7-p >= 4 > p
    int nIter   = min(TKV, q0max + 3200) / 64;  // CTA-wide iteration count
    int myIter  = min(TKV, q0 + 3200) / 64;     // this warp's active range

    // load Q: 256 rows x 128 halves = 4096 cp.async of 16B over 512 threads
#pragma unroll
    for (int i = 0; i < 8; i++) {
        int id = tid + i * 512;
        int r = id >> 4, c = id & 15;
        int grow = (r < 128) ? (p * 128 + r) : ((7 - p) * 128 + r - 128);
        cpa16(sbase + (unsigned)(r * AQ_S) * 2u + c * 16,
              Qp + ((size_t)bh * 1024 + grow) * 128 + c * 8);
    }

    auto issueKV = [&](int it) {
        int t0 = it * 64;
        int buf = it & 1;
        unsigned kb0 = (unsigned)(Q_SZ + buf * K_SZ) * 2u;
        unsigned vb0 = (unsigned)(Q_SZ + 2 * K_SZ + buf * V_SZ) * 2u;
#pragma unroll
        for (int i = 0; i < 2; i++) {
            int id = tid + i * 512;
            int r = id >> 4, c = id & 15;
            cpa16(kb0 + sbase + (unsigned)(r * AK_S) * 2u + c * 16,
                  Kp + ((size_t)bh * 4096 + t0 + r) * 128 + c * 8);
        }
#pragma unroll
        for (int i = 0; i < 2; i++) {
            int id = tid + i * 512;
            int r = id >> 3, c = id & 7;
            cpa16(vb0 + sbase + (unsigned)(r * AV_S) * 2u + c * 16,
                  Vp + ((size_t)bh * 128 + r) * 4096 + t0 + c * 8);
        }
        cpcommit();
    };

    issueKV(0);
    issueKV(1);

    float mrow[2] = { -1e30f, -1e30f };
    float lrow[2] = { 0.f, 0.f };
    float o[16][4];
#pragma unroll
    for (int nt = 0; nt < 16; nt++) { o[nt][0] = o[nt][1] = o[nt][2] = o[nt][3] = 0.f; }

    for (int it = 0; it < nIter; it++) {
        if (it + 1 < nIter) cpwait1(); else cpwait0();
        __syncthreads();

        if (it < myIter) {
            int t0 = it * 64;
            int buf = it & 1;
            const __half* Kb = smh + Q_SZ + buf * K_SZ;
            const __half* Vb = smh + Q_SZ + 2 * K_SZ + buf * V_SZ;

            // S = Q K^T (k=128 -> 8 k16 steps)
            float s[8][4];
#pragma unroll
            for (int nt = 0; nt < 8; nt++) { s[nt][0] = s[nt][1] = s[nt][2] = s[nt][3] = 0.f; }
#pragma unroll
            for (int ks = 0; ks < 8; ks++) {
                const __half* ap = Qs + (wq + g) * AQ_S + ks * 16 + t4 * 4;
                uint2 lo = *reinterpret_cast<const uint2*>(ap);
                uint2 hi = *reinterpret_cast<const uint2*>(ap + 8 * AQ_S);
                unsigned a0 = lo.x, a1 = hi.x, a2 = lo.y, a3 = hi.y;
#pragma unroll
                for (int nt = 0; nt < 8; nt++) {
                    uint2 bb = *reinterpret_cast<const uint2*>(
                        Kb + (nt * 8 + g) * AK_S + ks * 16 + t4 * 4);
                    mmaf16(s[nt], a0, a1, a2, a3, bb.x, bb.y);
                }
            }

            // scale + mask
            bool needmask = (t0 + 63 > q0 + CACHE);
            int rg0 = q0 + (wid & 7) * 16 + g, rg1 = rg0 + 8;
#pragma unroll
            for (int nt = 0; nt < 8; nt++) {
                s[nt][0] *= 0.125f; s[nt][1] *= 0.125f; s[nt][2] *= 0.125f; s[nt][3] *= 0.125f;
                if (needmask) {
                    int c0 = t0 + nt * 8 + 2 * t4;
                    if (c0     > rg0 + CACHE) s[nt][0] = -1e30f;
                    if (c0 + 1 > rg0 + CACHE) s[nt][1] = -1e30f;
                    if (c0     > rg1 + CACHE) s[nt][2] = -1e30f;
                    if (c0 + 1 > rg1 + CACHE) s[nt][3] = -1e30f;
                }
            }

            // online softmax
            float mx0 = -1e30f, mx1 = -1e30f;
#pragma unroll
            for (int nt = 0; nt < 8; nt++) {
                mx0 = fmaxf(mx0, fmaxf(s[nt][0], s[nt][1]));
                mx1 = fmaxf(mx1, fmaxf(s[nt][2], s[nt][3]));
            }
            mx0 = fmaxf(mx0, __shfl_xor_sync(0xffffffffu, mx0, 1));
            mx0 = fmaxf(mx0, __shfl_xor_sync(0xffffffffu, mx0, 2));
            mx1 = fmaxf(mx1, __shfl_xor_sync(0xffffffffu, mx1, 1));
            mx1 = fmaxf(mx1, __shfl_xor_sync(0xffffffffu, mx1, 2));
            float mn0 = fmaxf(mrow[0], mx0), mn1 = fmaxf(mrow[1], mx1);
            float al0 = __expf(mrow[0] - mn0), al1 = __expf(mrow[1] - mn1);
            float rs0 = 0.f, rs1 = 0.f;
#pragma unroll
            for (int nt = 0; nt < 8; nt++) {
                s[nt][0] = __expf(s[nt][0] - mn0);
                s[nt][1] = __expf(s[nt][1] - mn0);
                s[nt][2] = __expf(s[nt][2] - mn1);
                s[nt][3] = __expf(s[nt][3] - mn1);
                rs0 += s[nt][0] + s[nt][1];
                rs1 += s[nt][2] + s[nt][3];
            }
            rs0 += __shfl_xor_sync(0xffffffffu, rs0, 1);
            rs0 += __shfl_xor_sync(0xffffffffu, rs0, 2);
            rs1 += __shfl_xor_sync(0xffffffffu, rs1, 1);
            rs1 += __shfl_xor_sync(0xffffffffu, rs1, 2);
            lrow[0] = lrow[0] * al0 + rs0;
            lrow[1] = lrow[1] * al1 + rs1;
            mrow[0] = mn0; mrow[1] = mn1;
#pragma unroll
            for (int nt = 0; nt < 16; nt++) {
                o[nt][0] *= al0; o[nt][1] *= al0; o[nt][2] *= al1; o[nt][3] *= al1;
            }

            // O += P @ V (P in registers, identity kv order; V^T rows -> LDS.32 B frags)
#pragma unroll
            for (int kb = 0; kb < 4; kb++) {
                unsigned a0 = packh2(s[2 * kb][0], s[2 * kb][1]);
                unsigned a1 = packh2(s[2 * kb][2], s[2 * kb][3]);
                unsigned a2 = packh2(s[2 * kb + 1][0], s[2 * kb + 1][1]);
                unsigned a3 = packh2(s[2 * kb + 1][2], s[2 * kb + 1][3]);
#pragma unroll
                for (int nt = 0; nt < 16; nt++) {
                    const __half* vp = Vb + (nt * 8 + g) * AV_S + kb * 16 + 2 * t4;
                    unsigned b0 = *reinterpret_cast<const unsigned*>(vp);
                    unsigned b1 = *reinterpret_cast<const unsigned*>(vp + 8);
                    mmaf16(o[nt], a0, a1, a2, a3, b0, b1);
                }
            }
        }
        __syncthreads();
        if (it + 2 < nIter) issueKV(it + 2);
    }

    // epilogue — fp16 perm16 planes for the O-projection
    float il0 = 1.0f / lrow[0], il1 = 1.0f / lrow[1];
    int r0 = q0 + (wid & 7) * 16 + g;
    size_t rb0 = (size_t)(b * SEQ + r0) * HIDC;
    size_t rb1 = rb0 + (size_t)8 * HIDC;
#pragma unroll
    for (int nt = 0; nt < 16; nt++) {
        int d0 = nt * 8 + 2 * t4;
        __half* dst = (d0 < 64) ? ar : ai;
        int dd = d0 & 63;
        int hid = h * 64 + dd;
        int s = (hid & ~15) + slot16(hid & 15);
        *reinterpret_cast<__half2*>(dst + rb0 + s) =
            __floats2half2_rn(o[nt][0] * il0, o[nt][1] * il0);
        *reinterpret_cast<__half2*>(dst + rb1 + s) =
            __floats2half2_rn(o[nt][2] * il1, o[nt][3] * il1);
    }
}

// ---------------- launcher ----------------
extern "C" void kernel_launch(void* const* d_in, const int* in_sizes, int n_in,
                              void* d_out, int out_size) {
    const float* hr    = (const float*)d_in[0];
    const float* hi    = (const float*)d_in[1];
    const float* Kcr   = (const float*)d_in[2];
    const float* Kci   = (const float*)d_in[3];
    const float* Vcr   = (const float*)d_in[4];
    const float* Vci   = (const float*)d_in[5];
    const float* gamma = (const float*)d_in[6];
    const float* betar = (const float*)d_in[7];
    const float* betai = (const float*)d_in[8];
    const float* qbr = (const float*)d_in[11], *qbi = (const float*)d_in[12];
    const float* kbr = (const float*)d_in[15], *kbi = (const float*)d_in[16];
    const float* vbr = (const float*)d_in[19], *vbi = (const float*)d_in[20];
    const float* obr = (const float*)d_in[23], *obi = (const float*)d_in[24];

    float* out = (float*)d_out;
    float* outR = out + OFF_OUT_RE;
    float* outI = out + OFF_OUT_IM;
    float* nKr  = out + OFF_K_RE;
    float* nKi  = out + OFF_K_IM;
    float* nVr  = out + OFF_V_RE;
    float* nVi  = out + OFF_V_IM;

    __half *nrh, *nih, *arh, *aih, *qh, *kh, *vt, *wh;
    cudaGetSymbolAddress((void**)&nrh, g_nrh);
    cudaGetSymbolAddress((void**)&nih, g_nih);
    cudaGetSymbolAddress((void**)&arh, g_arh);
    cudaGetSymbolAddress((void**)&aih, g_aih);
    cudaGetSymbolAddress((void**)&qh, g_qh);
    cudaGetSymbolAddress((void**)&kh, g_kh);
    cudaGetSymbolAddress((void**)&vt, g_vt);
    cudaGetSymbolAddress((void**)&wh, g_wh);

    cudaFuncSetAttribute(attn_kernel, cudaFuncAttributeMaxDynamicSharedMemorySize, AT_SMEM);

    // weights -> fp16 perm16
    wconv_kernel<<<(int)((8u * 1024 * 1024) / 256), 256>>>(
        (const float*)d_in[9],  (const float*)d_in[10],
        (const float*)d_in[13], (const float*)d_in[14],
        (const float*)d_in[17], (const float*)d_in[18],
        (const float*)d_in[21], (const float*)d_in[22], wh);

    // K cache -> fp16 K plane (cache region)
    kcache_conv<<<(int)((2u * 3072 * 1024) / 256), 256>>>(Kcr, Kci, kh);

    // cache prefix copies (exact fp32)
    for (int b = 0; b < NBAT; b++) {
        size_t dofs = (size_t)b * TKV * HIDC;
        size_t sofs = (size_t)b * CACHE * HIDC;
        size_t bytes = (size_t)CACHE * HIDC * sizeof(float);
        cudaMemcpyAsync(nKr + dofs, Kcr + sofs, bytes, cudaMemcpyDeviceToDevice, 0);
        cudaMemcpyAsync(nKi + dofs, Kci + sofs, bytes, cudaMemcpyDeviceToDevice, 0);
        cudaMemcpyAsync(nVr + dofs, Vcr + sofs, bytes, cudaMemcpyDeviceToDevice, 0);
        cudaMemcpyAsync(nVi + dofs, Vci + sofs, bytes, cudaMemcpyDeviceToDevice, 0);
    }

    ln_kernel<<<MTOT, 256>>>(hr, hi, gamma, betar, betai, nrh, nih);

    constexpr size_t WPL = 1024u * 1024u;
    dim3 pg(HIDC / 64, MTOT / 128);  // (16, 16)
    proj_kernel<0><<<pg, 256>>>(nrh, nih, wh + 0 * WPL, wh + 1 * WPL,
                                qbr, qbi, nullptr, nullptr, qh, nullptr, nullptr);
    proj_kernel<1><<<pg, 256>>>(nrh, nih, wh + 2 * WPL, wh + 3 * WPL,
                                kbr, kbi, nKr, nKi, kh, nullptr, nullptr);
    proj_kernel<2><<<pg, 256>>>(nrh, nih, wh + 4 * WPL, wh + 5 * WPL,
                                vbr, vbi, nVr, nVi, nullptr, nullptr, nullptr);

    // build V^T fp16 plane from full fp32 V (cache copies + V proj must precede)
    vtrans_kernel<<<dim3(64, 32), 256>>>(nVr, nVi, vt);

    attn_kernel<<<128, 512, AT_SMEM>>>(qh, kh, vt, arh, aih);

    proj_kernel<3><<<pg, 256>>>(arh, aih, wh + 6 * WPL, wh + 7 * WPL,
                                obr, obi, outR, outI, nullptr, hr, hi);
}

// round 13
// speedup vs baseline: 1.0271x; 1.0271x over previous
#include <cuda_runtime.h>
#include <cuda_fp16.h>
#include <cstdint>
#include <cstddef>

// Problem constants
constexpr int HIDC  = 1024;
constexpr int SEQ   = 1024;
constexpr int NBAT  = 2;
constexpr int CACHE = 3072;
constexpr int TKV   = 4096;
constexpr int MTOT  = NBAT * SEQ;               // 2048 rows
constexpr size_t PLANE = (size_t)MTOT * HIDC;   // 2,097,152

// Output offsets (floats)
constexpr size_t OFF_OUT_RE = 0;
constexpr size_t OFF_OUT_IM = 2097152;
constexpr size_t OFF_K_RE   = 4194304;
constexpr size_t OFF_K_IM   = 12582912;
constexpr size_t OFF_V_RE   = 20971520;
constexpr size_t OFF_V_IM   = 29360128;

// Scratch (device globals — allocation-free)
__device__ __half g_nrh[PLANE];                  // LN out (fp16, perm16 over k)
__device__ __half g_nih[PLANE];
__device__ __half g_arh[PLANE];                  // attn out (fp16, perm16 over hid)
__device__ __half g_aih[PLANE];
__device__ __half g_qh[(size_t)32 * 1024 * 128]; // Q plane [bh][tok][128] perm16
__device__ __half g_kh[(size_t)32 * 4096 * 128]; // K plane [bh][tok][128] perm16
__device__ __half g_vt[(size_t)32 * 128 * 4096]; // V^T plane [bh][dim][tok]
__device__ __half g_wh[(size_t)8 * 1024 * 1024]; // weights fp16 perm16

// ---------------- helpers ----------------
__device__ __forceinline__ unsigned u32(float x) { return __float_as_uint(x); }

// perm16: reorder each 16-element k-group so a thread's fp16 fragment
// (k = {2t4, 2t4+1, 2t4+8, 2t4+9}) is 4 contiguous halves.
__device__ __forceinline__ int slot16(int w) {
    return ((w >> 1) & 3) * 4 + ((w >> 3) & 1) * 2 + (w & 1);
}
__device__ __forceinline__ int permidx(int k) { return (k & ~15) + slot16(k & 15); }

__device__ __forceinline__ unsigned packh2(float x, float y) {
    __half2 h = __floats2half2_rn(x, y);
    return *reinterpret_cast<unsigned*>(&h);
}

__device__ __forceinline__ void mmaf16(float* c, unsigned a0, unsigned a1, unsigned a2,
                                       unsigned a3, unsigned b0, unsigned b1) {
    asm("mma.sync.aligned.m16n8k16.row.col.f32.f16.f16.f32 "
        "{%0,%1,%2,%3},{%4,%5,%6,%7},{%8,%9},{%0,%1,%2,%3};"
        : "+f"(c[0]), "+f"(c[1]), "+f"(c[2]), "+f"(c[3])
        : "r"(a0), "r"(a1), "r"(a2), "r"(a3), "r"(b0), "r"(b1));
}

__device__ __forceinline__ void cpa16(unsigned dst, const void* src) {
    asm volatile("cp.async.cg.shared.global [%0], [%1], 16;" :: "r"(dst), "l"(src) : "memory");
}
__device__ __forceinline__ void cpcommit() { asm volatile("cp.async.commit_group;" ::: "memory"); }
__device__ __forceinline__ void cpwait1() { asm volatile("cp.async.wait_group 1;" ::: "memory"); }
__device__ __forceinline__ void cpwait0() { asm volatile("cp.async.wait_group 0;" ::: "memory"); }

// ---------------- weight convert: fp32 -> fp16 perm16 (sector-coalesced) ----------------
__global__ void wconv_kernel(const float* s0, const float* s1, const float* s2, const float* s3,
                             const float* s4, const float* s5, const float* s6, const float* s7,
                             __half* dst) {
    size_t i = (size_t)blockIdx.x * blockDim.x + threadIdx.x;   // 8M threads
    int p = (int)(i >> 20);
    size_t w = i & 1048575u;
    const float* sp;
    switch (p) {
        case 0: sp = s0; break; case 1: sp = s1; break;
        case 2: sp = s2; break; case 3: sp = s3; break;
        case 4: sp = s4; break; case 5: sp = s5; break;
        case 6: sp = s6; break; default: sp = s7; break;
    }
    int k = (int)(w & 1023);
    dst[(i & ~(size_t)1023) + permidx(k)] = __float2half(sp[w]);
}

// ---------------- K cache convert: fp32 [b][t][h][64] -> K plane (perm16) ----------------
__global__ void kcache_conv(const float* __restrict__ re, const float* __restrict__ im,
                            __half* __restrict__ Kh) {
    size_t i = (size_t)blockIdx.x * blockDim.x + threadIdx.x;   // 2*3072*1024
    int hd = (int)(i & 1023);
    int t  = (int)((i >> 10) % 3072u);
    int b  = (int)(i / (3072u * 1024u));
    int h = hd >> 6, d = hd & 63;
    size_t base = ((size_t)(b * 16 + h) * 4096 + t) * 128;
    int s = (d & ~15) + slot16(d & 15);
    Kh[base + s]      = __float2half(re[i]);
    Kh[base + 64 + s] = __float2half(im[i]);
}

// ---------------- V transpose: fp32 V [b][tok 4096][hid] -> fp16 V^T [bh][dim 128][tok] ----------------
__global__ void vtrans_kernel(const float* __restrict__ Vr, const float* __restrict__ Vi,
                              __half* __restrict__ Vt) {
    __shared__ float Tr[64][65];
    __shared__ float Ti[64][65];
    int tt = blockIdx.x;            // token tile 0..63
    int bh = blockIdx.y;            // 0..31
    int b = bh >> 4, h = bh & 15;
    int t0 = tt * 64;
    int tid = threadIdx.x;
#pragma unroll
    for (int i = 0; i < 16; i++) {
        int id = tid + i * 256;
        int tok = id >> 6, d = id & 63;
        size_t src = ((size_t)b * TKV + t0 + tok) * HIDC + h * 64 + d;
        Tr[tok][d] = Vr[src];
        Ti[tok][d] = Vi[src];
    }
    __syncthreads();
#pragma unroll
    for (int i = 0; i < 32; i++) {
        int id = tid + i * 256;
        int dim = id >> 6, tok = id & 63;
        float v = (dim < 64) ? Tr[tok][dim] : Ti[tok][dim - 64];
        Vt[((size_t)bh * 128 + dim) * 4096 + t0 + tok] = __float2half(v);
    }
}

// ---------------- Complex LayerNorm -> fp16 perm16 planes ----------------
__global__ void ln_kernel(const float* __restrict__ hr, const float* __restrict__ hi,
                          const float* __restrict__ gamma,
                          const float* __restrict__ betar, const float* __restrict__ betai,
                          __half* __restrict__ nr, __half* __restrict__ ni) {
    int row = blockIdx.x;
    int tid = threadIdx.x, lane = tid & 31, wid = tid >> 5;
    const float* pr = hr + (size_t)row * HIDC;
    const float* pi = hi + (size_t)row * HIDC;

    float vr[4], vi[4];
    float sr = 0.f, si = 0.f, sq = 0.f;
#pragma unroll
    for (int j = 0; j < 4; j++) {
        int e = tid + j * 256;
        vr[j] = pr[e]; vi[j] = pi[e];
        sr += vr[j]; si += vi[j]; sq += vr[j] * vr[j] + vi[j] * vi[j];
    }
#pragma unroll
    for (int o = 16; o; o >>= 1) {
        sr += __shfl_xor_sync(0xffffffffu, sr, o);
        si += __shfl_xor_sync(0xffffffffu, si, o);
        sq += __shfl_xor_sync(0xffffffffu, sq, o);
    }
    __shared__ float red[3][8];
    if (lane == 0) { red[0][wid] = sr; red[1][wid] = si; red[2][wid] = sq; }
    __syncthreads();
    float tsr = 0.f, tsi = 0.f, tsq = 0.f;
#pragma unroll
    for (int w = 0; w < 8; w++) { tsr += red[0][w]; tsi += red[1][w]; tsq += red[2][w]; }
    float mur = tsr * (1.0f / HIDC);
    float mui = tsi * (1.0f / HIDC);
    float var = tsq * (1.0f / HIDC) - mur * mur - mui * mui;
    float inv = rsqrtf(var + 1e-5f);
#pragma unroll
    for (int j = 0; j < 4; j++) {
        int e = tid + j * 256;
        float gm = gamma[e] * inv;
        int pe = permidx(e);
        nr[(size_t)row * HIDC + pe] = __float2half((vr[j] - mur) * gm + betar[e]);
        ni[(size_t)row * HIDC + pe] = __float2half((vi[j] - mui) * gm + betai[e]);
    }
}

// ---------------- Projection GEMM shapes ----------------
constexpr int PA_S = 40;                  // row stride in halves (80 B)
constexpr int PASZ = 128 * PA_S;          // 5120 halves
constexpr int PBSZ = 64 * PA_S;           // 2560 halves

// ---------------- Merged Q/K/V projection (one launch, mode = blockIdx.z) ----------------
// mode 0: Q -> fp16 Q plane; mode 1: K -> fp32 kv + fp16 K plane; mode 2: V -> fp32 kv.
__global__ void __launch_bounds__(256, 2)
qkv_kernel(const __half* __restrict__ A1, const __half* __restrict__ A2,
           const __half* __restrict__ WH,
           const float* __restrict__ qbr, const float* __restrict__ qbi,
           const float* __restrict__ kbr, const float* __restrict__ kbi,
           const float* __restrict__ vbr, const float* __restrict__ vbi,
           float* __restrict__ nKr, float* __restrict__ nKi,
           float* __restrict__ nVr, float* __restrict__ nVi,
           __half* __restrict__ qh, __half* __restrict__ kh) {
    __shared__ __half sm[2 * PASZ + 4 * PBSZ];   // 40960 B -> occ 2
    unsigned sbase = (unsigned)__cvta_generic_to_shared(sm);

    int mode = blockIdx.z;
    const __half* Wr = WH + ((size_t)(2 * mode) << 20);
    const __half* Wi = Wr + ((size_t)1 << 20);
    const float* brp = (mode == 0) ? qbr : (mode == 1) ? kbr : vbr;
    const float* bip = (mode == 0) ? qbi : (mode == 1) ? kbi : vbi;

    int tid = threadIdx.x, lane = tid & 31, wid = tid >> 5;
    int wm = wid & 3, wn = wid >> 2;
    int g = lane >> 2, t4 = lane & 3;
    int n0 = blockIdx.x * 64;
    int m0 = blockIdx.y * 128;

    float accR[2][4][4];
    float accI[2][4][4];
#pragma unroll
    for (int a = 0; a < 2; a++)
#pragma unroll
        for (int b = 0; b < 4; b++)
#pragma unroll
            for (int c = 0; c < 4; c++) { accR[a][b][c] = 0.f; accI[a][b][c] = 0.f; }

    auto issue = [&](int it) {
        bool ph2 = it >= 32;
        int ko = it * 32 - (ph2 ? 1024 : 0);
        const __half* Ap = ph2 ? A2 : A1;
        int buf = it & 1;
#pragma unroll
        for (int i = 0; i < 2; i++) {
            int id = tid + i * 256;
            int r = id >> 2, c = id & 3;
            cpa16(sbase + (unsigned)(buf * PASZ + r * PA_S) * 2u + c * 16,
                  Ap + (size_t)(m0 + r) * HIDC + ko + c * 8);
        }
#pragma unroll
        for (int i = 0; i < 2; i++) {
            int id = tid + i * 256;
            int pl = id >> 8, r = (id >> 2) & 63, c = id & 3;
            const __half* Wp = pl ? Wi : Wr;
            unsigned off = 2 * PASZ + (pl * 2 + buf) * PBSZ;
            cpa16(sbase + (off + (unsigned)(r * PA_S)) * 2u + c * 16,
                  Wp + (size_t)(n0 + r) * HIDC + ko + c * 8);
        }
        cpcommit();
    };

    issue(0);
    issue(1);

    for (int it = 0; it < 64; it++) {
        if (it < 63) cpwait1(); else cpwait0();
        __syncthreads();

        int buf = it & 1;
        bool ph2 = (it >= 32);
        const __half* Ab = sm + buf * PASZ;
        const __half* Bb = sm + 2 * PASZ + buf * PBSZ;

#pragma unroll
        for (int ks = 0; ks < 2; ks++) {
            unsigned af[2][4];
#pragma unroll
            for (int mt = 0; mt < 2; mt++) {
                const __half* ap = Ab + (wm * 32 + mt * 16 + g) * PA_S + ks * 16 + t4 * 4;
                uint2 lo = *reinterpret_cast<const uint2*>(ap);
                uint2 hi = *reinterpret_cast<const uint2*>(ap + 8 * PA_S);
                af[mt][0] = lo.x; af[mt][1] = hi.x; af[mt][2] = lo.y; af[mt][3] = hi.y;
            }
            unsigned naf[2][4];
            if (ph2) {
#pragma unroll
                for (int mt = 0; mt < 2; mt++)
#pragma unroll
                    for (int q = 0; q < 4; q++) naf[mt][q] = af[mt][q] ^ 0x80008000u;
            }
#pragma unroll
            for (int nt = 0; nt < 4; nt++) {
                const __half* bp = Bb + (wn * 32 + nt * 8 + g) * PA_S + ks * 16 + t4 * 4;
                uint2 bR = *reinterpret_cast<const uint2*>(bp);
                uint2 bI = *reinterpret_cast<const uint2*>(bp + 2 * PBSZ);
                if (ph2) {
#pragma unroll
                    for (int mt = 0; mt < 2; mt++) {
                        mmaf16(accR[mt][nt], naf[mt][0], naf[mt][1], naf[mt][2], naf[mt][3], bI.x, bI.y);
                        mmaf16(accI[mt][nt], af[mt][0], af[mt][1], af[mt][2], af[mt][3], bR.x, bR.y);
                    }
                } else {
#pragma unroll
                    for (int mt = 0; mt < 2; mt++) {
                        mmaf16(accR[mt][nt], af[mt][0], af[mt][1], af[mt][2], af[mt][3], bR.x, bR.y);
                        mmaf16(accI[mt][nt], af[mt][0], af[mt][1], af[mt][2], af[mt][3], bI.x, bI.y);
                    }
                }
            }
        }
        __syncthreads();
        if (it + 2 < 64) issue(it + 2);
    }

    // epilogue (mode-dispatched, block-uniform)
#pragma unroll
    for (int mt = 0; mt < 2; mt++) {
#pragma unroll
        for (int hrw = 0; hrw < 2; hrw++) {
            int r = m0 + wm * 32 + mt * 16 + g + hrw * 8;
            int bq = r >> 10, tk = r & 1023;
#pragma unroll
            for (int nt = 0; nt < 4; nt++) {
                int c0 = n0 + wn * 32 + nt * 8 + 2 * t4;
                float vr0 = accR[mt][nt][hrw * 2 + 0] + brp[c0];
                float vr1 = accR[mt][nt][hrw * 2 + 1] + brp[c0 + 1];
                float vi0 = accI[mt][nt][hrw * 2 + 0] + bip[c0];
                float vi1 = accI[mt][nt][hrw * 2 + 1] + bip[c0 + 1];
                int h = c0 >> 6, d = c0 & 63;
                int s = (d & ~15) + slot16(d & 15);

                if (mode == 0) {
                    size_t base = ((size_t)(bq * 16 + h) * 1024 + tk) * 128;
                    *reinterpret_cast<__half2*>(qh + base + s) = __floats2half2_rn(vr0, vr1);
                    *reinterpret_cast<__half2*>(qh + base + 64 + s) = __floats2half2_rn(vi0, vi1);
                } else if (mode == 1) {
                    size_t orow = (size_t)bq * TKV + CACHE + tk;
                    nKr[orow * HIDC + c0] = vr0;  nKr[orow * HIDC + c0 + 1] = vr1;
                    nKi[orow * HIDC + c0] = vi0;  nKi[orow * HIDC + c0 + 1] = vi1;
                    size_t base = ((size_t)(bq * 16 + h) * 4096 + CACHE + tk) * 128;
                    *reinterpret_cast<__half2*>(kh + base + s) = __floats2half2_rn(vr0, vr1);
                    *reinterpret_cast<__half2*>(kh + base + 64 + s) = __floats2half2_rn(vi0, vi1);
                } else {
                    size_t orow = (size_t)bq * TKV + CACHE + tk;
                    nVr[orow * HIDC + c0] = vr0;  nVr[orow * HIDC + c0 + 1] = vr1;
                    nVi[orow * HIDC + c0] = vi0;  nVi[orow * HIDC + c0 + 1] = vi1;
                }
            }
        }
    }
}

// ---------------- O projection (fp32 out + residual) ----------------
__global__ void __launch_bounds__(256, 2)
oproj_kernel(const __half* __restrict__ A1, const __half* __restrict__ A2,
             const __half* __restrict__ Wr, const __half* __restrict__ Wi,
             const float* __restrict__ brp, const float* __restrict__ bip,
             float* __restrict__ Or, float* __restrict__ Oi,
             const float* __restrict__ Rr, const float* __restrict__ Ri) {
    __shared__ __half sm[2 * PASZ + 4 * PBSZ];
    unsigned sbase = (unsigned)__cvta_generic_to_shared(sm);

    int tid = threadIdx.x, lane = tid & 31, wid = tid >> 5;
    int wm = wid & 3, wn = wid >> 2;
    int g = lane >> 2, t4 = lane & 3;
    int n0 = blockIdx.x * 64;
    int m0 = blockIdx.y * 128;

    float accR[2][4][4];
    float accI[2][4][4];
#pragma unroll
    for (int a = 0; a < 2; a++)
#pragma unroll
        for (int b = 0; b < 4; b++)
#pragma unroll
            for (int c = 0; c < 4; c++) { accR[a][b][c] = 0.f; accI[a][b][c] = 0.f; }

    auto issue = [&](int it) {
        bool ph2 = it >= 32;
        int ko = it * 32 - (ph2 ? 1024 : 0);
        const __half* Ap = ph2 ? A2 : A1;
        int buf = it & 1;
#pragma unroll
        for (int i = 0; i < 2; i++) {
            int id = tid + i * 256;
            int r = id >> 2, c = id & 3;
            cpa16(sbase + (unsigned)(buf * PASZ + r * PA_S) * 2u + c * 16,
                  Ap + (size_t)(m0 + r) * HIDC + ko + c * 8);
        }
#pragma unroll
        for (int i = 0; i < 2; i++) {
            int id = tid + i * 256;
            int pl = id >> 8, r = (id >> 2) & 63, c = id & 3;
            const __half* Wp = pl ? Wi : Wr;
            unsigned off = 2 * PASZ + (pl * 2 + buf) * PBSZ;
            cpa16(sbase + (off + (unsigned)(r * PA_S)) * 2u + c * 16,
                  Wp + (size_t)(n0 + r) * HIDC + ko + c * 8);
        }
        cpcommit();
    };

    issue(0);
    issue(1);

    for (int it = 0; it < 64; it++) {
        if (it < 63) cpwait1(); else cpwait0();
        __syncthreads();

        int buf = it & 1;
        bool ph2 = (it >= 32);
        const __half* Ab = sm + buf * PASZ;
        const __half* Bb = sm + 2 * PASZ + buf * PBSZ;

#pragma unroll
        for (int ks = 0; ks < 2; ks++) {
            unsigned af[2][4];
#pragma unroll
            for (int mt = 0; mt < 2; mt++) {
                const __half* ap = Ab + (wm * 32 + mt * 16 + g) * PA_S + ks * 16 + t4 * 4;
                uint2 lo = *reinterpret_cast<const uint2*>(ap);
                uint2 hi = *reinterpret_cast<const uint2*>(ap + 8 * PA_S);
                af[mt][0] = lo.x; af[mt][1] = hi.x; af[mt][2] = lo.y; af[mt][3] = hi.y;
            }
            unsigned naf[2][4];
            if (ph2) {
#pragma unroll
                for (int mt = 0; mt < 2; mt++)
#pragma unroll
                    for (int q = 0; q < 4; q++) naf[mt][q] = af[mt][q] ^ 0x80008000u;
            }
#pragma unroll
            for (int nt = 0; nt < 4; nt++) {
                const __half* bp = Bb + (wn * 32 + nt * 8 + g) * PA_S + ks * 16 + t4 * 4;
                uint2 bR = *reinterpret_cast<const uint2*>(bp);
                uint2 bI = *reinterpret_cast<const uint2*>(bp + 2 * PBSZ);
                if (ph2) {
#pragma unroll
                    for (int mt = 0; mt < 2; mt++) {
                        mmaf16(accR[mt][nt], naf[mt][0], naf[mt][1], naf[mt][2], naf[mt][3], bI.x, bI.y);
                        mmaf16(accI[mt][nt], af[mt][0], af[mt][1], af[mt][2], af[mt][3], bR.x, bR.y);
                    }
                } else {
#pragma unroll
                    for (int mt = 0; mt < 2; mt++) {
                        mmaf16(accR[mt][nt], af[mt][0], af[mt][1], af[mt][2], af[mt][3], bR.x, bR.y);
                        mmaf16(accI[mt][nt], af[mt][0], af[mt][1], af[mt][2], af[mt][3], bI.x, bI.y);
                    }
                }
            }
        }
        __syncthreads();
        if (it + 2 < 64) issue(it + 2);
    }

#pragma unroll
    for (int mt = 0; mt < 2; mt++) {
#pragma unroll
        for (int hrw = 0; hrw < 2; hrw++) {
            int r = m0 + wm * 32 + mt * 16 + g + hrw * 8;
#pragma unroll
            for (int nt = 0; nt < 4; nt++) {
                int c0 = n0 + wn * 32 + nt * 8 + 2 * t4;
                float vr0 = accR[mt][nt][hrw * 2 + 0] + brp[c0];
                float vr1 = accR[mt][nt][hrw * 2 + 1] + brp[c0 + 1];
                float vi0 = accI[mt][nt][hrw * 2 + 0] + bip[c0];
                float vi1 = accI[mt][nt][hrw * 2 + 1] + bip[c0 + 1];
                size_t rowo = (size_t)r * HIDC;
                Or[rowo + c0]     = vr0 + Rr[rowo + c0];
                Or[rowo + c0 + 1] = vr1 + Rr[rowo + c0 + 1];
                Oi[rowo + c0]     = vi0 + Ri[rowo + c0];
                Oi[rowo + c0 + 1] = vi1 + Ri[rowo + c0 + 1];
            }
        }
    }
}

// ---------------- Flash attention (fp16 mma, occ 1, balanced pairs — R11) ----------------
constexpr int AQ_S = 136;                 // halves
constexpr int AK_S = 136;
constexpr int AV_S = 72;                  // V^T rows (64 kv + 8 pad)
constexpr int Q_SZ = 128 * AQ_S;          // 17408 halves
constexpr int K_SZ = 64 * AK_S;           // 8704
constexpr int V_SZ = 128 * AV_S;          // 9216
constexpr int AT_SMEM = (Q_SZ + 2 * K_SZ + 2 * V_SZ) * 2;   // 106496 bytes

__global__ void __launch_bounds__(256, 1)
attn_kernel(const __half* __restrict__ Qp, const __half* __restrict__ Kp,
            const __half* __restrict__ Vp,
            __half* __restrict__ ar, __half* __restrict__ ai) {
    extern __shared__ __half smh[];
    __half* Qs = smh;
    unsigned sbase = (unsigned)__cvta_generic_to_shared(smh);

    int tid = threadIdx.x, lane = tid & 31, wid = tid >> 5;
    int g = lane >> 2, t4 = lane & 3;
    int bh = blockIdx.x >> 2;
    int p  = blockIdx.x & 3;
    int b = bh >> 4, h = bh & 15;
    int wq = wid * 16;

    for (int rep = 0; rep < 2; rep++) {
        int qb = rep ? (7 - p) : p;
        int q0 = qb * 128;
        int t_end = min(TKV, q0 + 3200);
        int nIter = t_end / 64;

        // Q tile (joins group 0)
#pragma unroll
        for (int i = 0; i < 8; i++) {
            int id = tid + i * 256;
            int r = id >> 4, c = id & 15;
            cpa16(sbase + (unsigned)(r * AQ_S) * 2u + c * 16,
                  Qp + ((size_t)bh * 1024 + q0 + r) * 128 + c * 8);
        }

        auto issueKV = [&](int it) {
            int t0 = it * 64;
            int buf = it & 1;
            unsigned kb0 = (unsigned)(Q_SZ + buf * K_SZ) * 2u;
            unsigned vb0 = (unsigned)(Q_SZ + 2 * K_SZ + buf * V_SZ) * 2u;
#pragma unroll
            for (int i = 0; i < 4; i++) {
                int id = tid + i * 256;
                int r = id >> 4, c = id & 15;
                cpa16(kb0 + sbase + (unsigned)(r * AK_S) * 2u + c * 16,
                      Kp + ((size_t)bh * 4096 + t0 + r) * 128 + c * 8);
            }
#pragma unroll
            for (int i = 0; i < 4; i++) {
                int id = tid + i * 256;
                int r = id >> 3, c = id & 7;
                cpa16(vb0 + sbase + (unsigned)(r * AV_S) * 2u + c * 16,
                      Vp + ((size_t)bh * 128 + r) * 4096 + t0 + c * 8);
            }
            cpcommit();
        };

        issueKV(0);
        issueKV(1);

        float mrow[2] = { -1e30f, -1e30f };
        float lrow[2] = { 0.f, 0.f };
        float o[16][4];
#pragma unroll
        for (int nt = 0; nt < 16; nt++) { o[nt][0] = o[nt][1] = o[nt][2] = o[nt][3] = 0.f; }

        for (int it = 0; it < nIter; it++) {
            if (it + 1 < nIter) cpwait1(); else cpwait0();
            __syncthreads();

            int t0 = it * 64;
            int buf = it & 1;
            const __half* Kb = smh + Q_SZ + buf * K_SZ;
            const __half* Vb = smh + Q_SZ + 2 * K_SZ + buf * V_SZ;

            // S = Q K^T (k=128 -> 8 k16 steps)
            float s[8][4];
#pragma unroll
            for (int nt = 0; nt < 8; nt++) { s[nt][0] = s[nt][1] = s[nt][2] = s[nt][3] = 0.f; }
#pragma unroll
            for (int ks = 0; ks < 8; ks++) {
                const __half* ap = Qs + (wq + g) * AQ_S + ks * 16 + t4 * 4;
                uint2 lo = *reinterpret_cast<const uint2*>(ap);
                uint2 hi = *reinterpret_cast<const uint2*>(ap + 8 * AQ_S);
                unsigned a0 = lo.x, a1 = hi.x, a2 = lo.y, a3 = hi.y;
#pragma unroll
                for (int nt = 0; nt < 8; nt++) {
                    uint2 bb = *reinterpret_cast<const uint2*>(
                        Kb + (nt * 8 + g) * AK_S + ks * 16 + t4 * 4);
                    mmaf16(s[nt], a0, a1, a2, a3, bb.x, bb.y);
                }
            }

            // scale + mask
            bool needmask = (t0 + 63 > q0 + CACHE);
            int rg0 = q0 + wq + g, rg1 = rg0 + 8;
#pragma unroll
            for (int nt = 0; nt < 8; nt++) {
                s[nt][0] *= 0.125f; s[nt][1] *= 0.125f; s[nt][2] *= 0.125f; s[nt][3] *= 0.125f;
                if (needmask) {
                    int c0 = t0 + nt * 8 + 2 * t4;
                    if (c0     > rg0 + CACHE) s[nt][0] = -1e30f;
                    if (c0 + 1 > rg0 + CACHE) s[nt][1] = -1e30f;
                    if (c0     > rg1 + CACHE) s[nt][2] = -1e30f;
                    if (c0 + 1 > rg1 + CACHE) s[nt][3] = -1e30f;
                }
            }

            // online softmax
            float mx0 = -1e30f, mx1 = -1e30f;
#pragma unroll
            for (int nt = 0; nt < 8; nt++) {
                mx0 = fmaxf(mx0, fmaxf(s[nt][0], s[nt][1]));
                mx1 = fmaxf(mx1, fmaxf(s[nt][2], s[nt][3]));
            }
            mx0 = fmaxf(mx0, __shfl_xor_sync(0xffffffffu, mx0, 1));
            mx0 = fmaxf(mx0, __shfl_xor_sync(0xffffffffu, mx0, 2));
            mx1 = fmaxf(mx1, __shfl_xor_sync(0xffffffffu, mx1, 1));
            mx1 = fmaxf(mx1, __shfl_xor_sync(0xffffffffu, mx1, 2));
            float mn0 = fmaxf(mrow[0], mx0), mn1 = fmaxf(mrow[1], mx1);
            float al0 = __expf(mrow[0] - mn0), al1 = __expf(mrow[1] - mn1);
            float rs0 = 0.f, rs1 = 0.f;
#pragma unroll
            for (int nt = 0; nt < 8; nt++) {
                s[nt][0] = __expf(s[nt][0] - mn0);
                s[nt][1] = __expf(s[nt][1] - mn0);
                s[nt][2] = __expf(s[nt][2] - mn1);
                s[nt][3] = __expf(s[nt][3] - mn1);
                rs0 += s[nt][0] + s[nt][1];
                rs1 += s[nt][2] + s[nt][3];
            }
            rs0 += __shfl_xor_sync(0xffffffffu, rs0, 1);
            rs0 += __shfl_xor_sync(0xffffffffu, rs0, 2);
            rs1 += __shfl_xor_sync(0xffffffffu, rs1, 1);
            rs1 += __shfl_xor_sync(0xffffffffu, rs1, 2);
            lrow[0] = lrow[0] * al0 + rs0;
            lrow[1] = lrow[1] * al1 + rs1;
            mrow[0] = mn0; mrow[1] = mn1;
#pragma unroll
            for (int nt = 0; nt < 16; nt++) {
                o[nt][0] *= al0; o[nt][1] *= al0; o[nt][2] *= al1; o[nt][3] *= al1;
            }

            // O += P @ V (P in registers, identity kv order; V^T rows -> LDS.32 B frags)
#pragma unroll
            for (int kb = 0; kb < 4; kb++) {
                unsigned a0 = packh2(s[2 * kb][0], s[2 * kb][1]);
                unsigned a1 = packh2(s[2 * kb][2], s[2 * kb][3]);
                unsigned a2 = packh2(s[2 * kb + 1][0], s[2 * kb + 1][1]);
                unsigned a3 = packh2(s[2 * kb + 1][2], s[2 * kb + 1][3]);
#pragma unroll
                for (int nt = 0; nt < 16; nt++) {
                    const __half* vp = Vb + (nt * 8 + g) * AV_S + kb * 16 + 2 * t4;
                    unsigned b0 = *reinterpret_cast<const unsigned*>(vp);
                    unsigned b1 = *reinterpret_cast<const unsigned*>(vp + 8);
                    mmaf16(o[nt], a0, a1, a2, a3, b0, b1);
                }
            }
            __syncthreads();
            if (it + 2 < nIter) issueKV(it + 2);
        }

        // epilogue — fp16 perm16 planes for the O-projection
        float il0 = 1.0f / lrow[0], il1 = 1.0f / lrow[1];
        int r0 = q0 + wq + g;
        size_t rb0 = (size_t)(b * SEQ + r0) * HIDC;
        size_t rb1 = rb0 + (size_t)8 * HIDC;
#pragma unroll
        for (int nt = 0; nt < 16; nt++) {
            int d0 = nt * 8 + 2 * t4;
            __half* dst = (d0 < 64) ? ar : ai;
            int dd = d0 & 63;
            int hid = h * 64 + dd;
            int s = (hid & ~15) + slot16(hid & 15);
            *reinterpret_cast<__half2*>(dst + rb0 + s) =
                __floats2half2_rn(o[nt][0] * il0, o[nt][1] * il0);
            *reinterpret_cast<__half2*>(dst + rb1 + s) =
                __floats2half2_rn(o[nt][2] * il1, o[nt][3] * il1);
        }
    }
}

// ---------------- launcher ----------------
extern "C" void kernel_launch(void* const* d_in, const int* in_sizes, int n_in,
                              void* d_out, int out_size) {
    const float* hr    = (const float*)d_in[0];
    const float* hi    = (const float*)d_in[1];
    const float* Kcr   = (const float*)d_in[2];
    const float* Kci   = (const float*)d_in[3];
    const float* Vcr   = (const float*)d_in[4];
    const float* Vci   = (const float*)d_in[5];
    const float* gamma = (const float*)d_in[6];
    const float* betar = (const float*)d_in[7];
    const float* betai = (const float*)d_in[8];
    const float* qbr = (const float*)d_in[11], *qbi = (const float*)d_in[12];
    const float* kbr = (const float*)d_in[15], *kbi = (const float*)d_in[16];
    const float* vbr = (const float*)d_in[19], *vbi = (const float*)d_in[20];
    const float* obr = (const float*)d_in[23], *obi = (const float*)d_in[24];

    float* out = (float*)d_out;
    float* outR = out + OFF_OUT_RE;
    float* outI = out + OFF_OUT_IM;
    float* nKr  = out + OFF_K_RE;
    float* nKi  = out + OFF_K_IM;
    float* nVr  = out + OFF_V_RE;
    float* nVi  = out + OFF_V_IM;

    __half *nrh, *nih, *arh, *aih, *qh, *kh, *vt, *wh;
    cudaGetSymbolAddress((void**)&nrh, g_nrh);
    cudaGetSymbolAddress((void**)&nih, g_nih);
    cudaGetSymbolAddress((void**)&arh, g_arh);
    cudaGetSymbolAddress((void**)&aih, g_aih);
    cudaGetSymbolAddress((void**)&qh, g_qh);
    cudaGetSymbolAddress((void**)&kh, g_kh);
    cudaGetSymbolAddress((void**)&vt, g_vt);
    cudaGetSymbolAddress((void**)&wh, g_wh);

    cudaFuncSetAttribute(attn_kernel, cudaFuncAttributeMaxDynamicSharedMemorySize, AT_SMEM);

    // weights -> fp16 perm16
    wconv_kernel<<<(int)((8u * 1024 * 1024) / 256), 256>>>(
        (const float*)d_in[9],  (const float*)d_in[10],
        (const float*)d_in[13], (const float*)d_in[14],
        (const float*)d_in[17], (const float*)d_in[18],
        (const float*)d_in[21], (const float*)d_in[22], wh);

    // K cache -> fp16 K plane (cache region)
    kcache_conv<<<(int)((2u * 3072 * 1024) / 256), 256>>>(Kcr, Kci, kh);

    // cache prefix copies (exact fp32)
    for (int b = 0; b < NBAT; b++) {
        size_t dofs = (size_t)b * TKV * HIDC;
        size_t sofs = (size_t)b * CACHE * HIDC;
        size_t bytes = (size_t)CACHE * HIDC * sizeof(float);
        cudaMemcpyAsync(nKr + dofs, Kcr + sofs, bytes, cudaMemcpyDeviceToDevice, 0);
        cudaMemcpyAsync(nKi + dofs, Kci + sofs, bytes, cudaMemcpyDeviceToDevice, 0);
        cudaMemcpyAsync(nVr + dofs, Vcr + sofs, bytes, cudaMemcpyDeviceToDevice, 0);
        cudaMemcpyAsync(nVi + dofs, Vci + sofs, bytes, cudaMemcpyDeviceToDevice, 0);
    }

    ln_kernel<<<MTOT, 256>>>(hr, hi, gamma, betar, betai, nrh, nih);

    // merged Q/K/V projection: one launch, 768 CTAs (mode = blockIdx.z)
    qkv_kernel<<<dim3(HIDC / 64, MTOT / 128, 3), 256>>>(
        nrh, nih, wh, qbr, qbi, kbr, kbi, vbr, vbi,
        nKr, nKi, nVr, nVi, qh, kh);

    // build V^T fp16 plane from full fp32 V (cache copies + V proj must precede)
    vtrans_kernel<<<dim3(64, 32), 256>>>(nVr, nVi, vt);

    attn_kernel<<<128, 256, AT_SMEM>>>(qh, kh, vt, arh, aih);

    constexpr size_t WPL = 1024u * 1024u;
    oproj_kernel<<<dim3(HIDC / 64, MTOT / 128), 256>>>(
        arh, aih, wh + 6 * WPL, wh + 7 * WPL, obr, obi, outR, outI, hr, hi);
}

// round 15
// speedup vs baseline: 1.0934x; 1.0646x over previous
#include <cuda_runtime.h>
#include <cuda_fp16.h>
#include <cstdint>
#include <cstddef>

// Problem constants
constexpr int HIDC  = 1024;
constexpr int SEQ   = 1024;
constexpr int NBAT  = 2;
constexpr int CACHE = 3072;
constexpr int TKV   = 4096;
constexpr int MTOT  = NBAT * SEQ;               // 2048 rows
constexpr size_t PLANE = (size_t)MTOT * HIDC;   // 2,097,152

// Output offsets (floats)
constexpr size_t OFF_OUT_RE = 0;
constexpr size_t OFF_OUT_IM = 2097152;
constexpr size_t OFF_K_RE   = 4194304;
constexpr size_t OFF_K_IM   = 12582912;
constexpr size_t OFF_V_RE   = 20971520;
constexpr size_t OFF_V_IM   = 29360128;

// Scratch (device globals — allocation-free)
__device__ __half g_nrh[PLANE];                  // LN out (fp16, perm16 over k)
__device__ __half g_nih[PLANE];
__device__ __half g_arh[PLANE];                  // attn out (fp16, perm16 over hid)
__device__ __half g_aih[PLANE];
__device__ __half g_qh[(size_t)32 * 1024 * 128]; // Q plane [bh][tok][128] perm16
__device__ __half g_kh[(size_t)32 * 4096 * 128]; // K plane [bh][tok][128] perm16
__device__ __half g_vt[(size_t)32 * 128 * 4096]; // V^T plane [bh][dim][tok]
__device__ __half g_wh[(size_t)8 * 1024 * 1024]; // weights fp16 perm16

// ---------------- helpers ----------------
__device__ __forceinline__ unsigned u32(float x) { return __float_as_uint(x); }

// perm16: reorder each 16-element k-group so a thread's fp16 A/B fragment
// (k = {2t4, 2t4+1, 2t4+8, 2t4+9}) is 4 contiguous halves.
__device__ __forceinline__ int slot16(int w) {
    return ((w >> 1) & 3) * 4 + ((w >> 3) & 1) * 2 + (w & 1);
}
__device__ __forceinline__ int permidx(int k) { return (k & ~15) + slot16(k & 15); }

__device__ __forceinline__ unsigned packh2(float x, float y) {
    __half2 h = __floats2half2_rn(x, y);
    return *reinterpret_cast<unsigned*>(&h);
}

__device__ __forceinline__ void mmaf16(float* c, unsigned a0, unsigned a1, unsigned a2,
                                       unsigned a3, unsigned b0, unsigned b1) {
    asm("mma.sync.aligned.m16n8k16.row.col.f32.f16.f16.f32 "
        "{%0,%1,%2,%3},{%4,%5,%6,%7},{%8,%9},{%0,%1,%2,%3};"
        : "+f"(c[0]), "+f"(c[1]), "+f"(c[2]), "+f"(c[3])
        : "r"(a0), "r"(a1), "r"(a2), "r"(a3), "r"(b0), "r"(b1));
}

__device__ __forceinline__ void cpa16(unsigned dst, const void* src) {
    asm volatile("cp.async.cg.shared.global [%0], [%1], 16;" :: "r"(dst), "l"(src) : "memory");
}
__device__ __forceinline__ void cpcommit() { asm volatile("cp.async.commit_group;" ::: "memory"); }
__device__ __forceinline__ void cpwait1() { asm volatile("cp.async.wait_group 1;" ::: "memory"); }
__device__ __forceinline__ void cpwait0() { asm volatile("cp.async.wait_group 0;" ::: "memory"); }

// ---------------- weight convert: fp32 -> fp16 perm16 (sector-coalesced) ----------------
__global__ void wconv_kernel(const float* s0, const float* s1, const float* s2, const float* s3,
                             const float* s4, const float* s5, const float* s6, const float* s7,
                             __half* dst) {
    size_t i = (size_t)blockIdx.x * blockDim.x + threadIdx.x;   // 8M threads
    int p = (int)(i >> 20);
    size_t w = i & 1048575u;
    const float* sp;
    switch (p) {
        case 0: sp = s0; break; case 1: sp = s1; break;
        case 2: sp = s2; break; case 3: sp = s3; break;
        case 4: sp = s4; break; case 5: sp = s5; break;
        case 6: sp = s6; break; default: sp = s7; break;
    }
    int k = (int)(w & 1023);
    dst[(i & ~(size_t)1023) + permidx(k)] = __float2half(sp[w]);
}

// ---------------- K cache convert: fp32 [b][t][h][64] -> K plane (perm16) ----------------
__global__ void kcache_conv(const float* __restrict__ re, const float* __restrict__ im,
                            __half* __restrict__ Kh) {
    size_t i = (size_t)blockIdx.x * blockDim.x + threadIdx.x;   // 2*3072*1024
    int hd = (int)(i & 1023);
    int t  = (int)((i >> 10) % 3072u);
    int b  = (int)(i / (3072u * 1024u));
    int h = hd >> 6, d = hd & 63;
    size_t base = ((size_t)(b * 16 + h) * 4096 + t) * 128;
    int s = (d & ~15) + slot16(d & 15);
    Kh[base + s]      = __float2half(re[i]);
    Kh[base + 64 + s] = __float2half(im[i]);
}

// ---------------- V transpose: fp32 V [b][tok 4096][hid] -> fp16 V^T [bh][dim 128][tok] ----------------
__global__ void vtrans_kernel(const float* __restrict__ Vr, const float* __restrict__ Vi,
                              __half* __restrict__ Vt) {
    __shared__ float Tr[64][65];
    __shared__ float Ti[64][65];
    int tt = blockIdx.x;            // token tile 0..63
    int bh = blockIdx.y;            // 0..31
    int b = bh >> 4, h = bh & 15;
    int t0 = tt * 64;
    int tid = threadIdx.x;
#pragma unroll
    for (int i = 0; i < 16; i++) {
        int id = tid + i * 256;
        int tok = id >> 6, d = id & 63;
        size_t src = ((size_t)b * TKV + t0 + tok) * HIDC + h * 64 + d;
        Tr[tok][d] = Vr[src];
        Ti[tok][d] = Vi[src];
    }
    __syncthreads();
#pragma unroll
    for (int i = 0; i < 32; i++) {
        int id = tid + i * 256;
        int dim = id >> 6, tok = id & 63;
        float v = (dim < 64) ? Tr[tok][dim] : Ti[tok][dim - 64];
        Vt[((size_t)bh * 128 + dim) * 4096 + t0 + tok] = __float2half(v);
    }
}

// ---------------- Complex LayerNorm -> fp16 perm16 planes ----------------
__global__ void ln_kernel(const float* __restrict__ hr, const float* __restrict__ hi,
                          const float* __restrict__ gamma,
                          const float* __restrict__ betar, const float* __restrict__ betai,
                          __half* __restrict__ nr, __half* __restrict__ ni) {
    int row = blockIdx.x;
    int tid = threadIdx.x, lane = tid & 31, wid = tid >> 5;
    const float* pr = hr + (size_t)row * HIDC;
    const float* pi = hi + (size_t)row * HIDC;

    float vr[4], vi[4];
    float sr = 0.f, si = 0.f, sq = 0.f;
#pragma unroll
    for (int j = 0; j < 4; j++) {
        int e = tid + j * 256;
        vr[j] = pr[e]; vi[j] = pi[e];
        sr += vr[j]; si += vi[j]; sq += vr[j] * vr[j] + vi[j] * vi[j];
    }
#pragma unroll
    for (int o = 16; o; o >>= 1) {
        sr += __shfl_xor_sync(0xffffffffu, sr, o);
        si += __shfl_xor_sync(0xffffffffu, si, o);
        sq += __shfl_xor_sync(0xffffffffu, sq, o);
    }
    __shared__ float red[3][8];
    if (lane == 0) { red[0][wid] = sr; red[1][wid] = si; red[2][wid] = sq; }
    __syncthreads();
    float tsr = 0.f, tsi = 0.f, tsq = 0.f;
#pragma unroll
    for (int w = 0; w < 8; w++) { tsr += red[0][w]; tsi += red[1][w]; tsq += red[2][w]; }
    float mur = tsr * (1.0f / HIDC);
    float mui = tsi * (1.0f / HIDC);
    float var = tsq * (1.0f / HIDC) - mur * mur - mui * mui;
    float inv = rsqrtf(var + 1e-5f);
#pragma unroll
    for (int j = 0; j < 4; j++) {
        int e = tid + j * 256;
        float gm = gamma[e] * inv;
        int pe = permidx(e);
        nr[(size_t)row * HIDC + pe] = __float2half((vr[j] - mur) * gm + betar[e]);
        ni[(size_t)row * HIDC + pe] = __float2half((vi[j] - mui) * gm + betai[e]);
    }
}

// ---------------- Projection GEMM shapes ----------------
constexpr int PA_S = 40;                  // row stride in halves (80 B)
constexpr int PASZ = 128 * PA_S;          // 5120 halves
constexpr int PBSZ = 64 * PA_S;           // 2560 halves

// ---------------- Merged Q/K/V projection (one launch, mode = blockIdx.z) ----------------
// mode 0: Q -> fp16 Q plane; mode 1: K -> fp32 kv + fp16 K plane; mode 2: V -> fp32 kv.
__global__ void __launch_bounds__(256, 2)
qkv_kernel(const __half* __restrict__ A1, const __half* __restrict__ A2,
           const __half* __restrict__ WH,
           const float* __restrict__ qbr, const float* __restrict__ qbi,
           const float* __restrict__ kbr, const float* __restrict__ kbi,
           const float* __restrict__ vbr, const float* __restrict__ vbi,
           float* __restrict__ nKr, float* __restrict__ nKi,
           float* __restrict__ nVr, float* __restrict__ nVi,
           __half* __restrict__ qh, __half* __restrict__ kh) {
    __shared__ __half sm[2 * PASZ + 4 * PBSZ];   // 40960 B -> occ 2
    unsigned sbase = (unsigned)__cvta_generic_to_shared(sm);

    int mode = blockIdx.z;
    const __half* Wr = WH + ((size_t)(2 * mode) << 20);
    const __half* Wi = Wr + ((size_t)1 << 20);
    const float* brp = (mode == 0) ? qbr : (mode == 1) ? kbr : vbr;
    const float* bip = (mode == 0) ? qbi : (mode == 1) ? kbi : vbi;

    int tid = threadIdx.x, lane = tid & 31, wid = tid >> 5;
    int wm = wid & 3, wn = wid >> 2;
    int g = lane >> 2, t4 = lane & 3;
    int n0 = blockIdx.x * 64;
    int m0 = blockIdx.y * 128;

    float accR[2][4][4];
    float accI[2][4][4];
#pragma unroll
    for (int a = 0; a < 2; a++)
#pragma unroll
        for (int b = 0; b < 4; b++)
#pragma unroll
            for (int c = 0; c < 4; c++) { accR[a][b][c] = 0.f; accI[a][b][c] = 0.f; }

    auto issue = [&](int it) {
        bool ph2 = it >= 32;
        int ko = it * 32 - (ph2 ? 1024 : 0);
        const __half* Ap = ph2 ? A2 : A1;
        int buf = it & 1;
#pragma unroll
        for (int i = 0; i < 2; i++) {
            int id = tid + i * 256;
            int r = id >> 2, c = id & 3;
            cpa16(sbase + (unsigned)(buf * PASZ + r * PA_S) * 2u + c * 16,
                  Ap + (size_t)(m0 + r) * HIDC + ko + c * 8);
        }
#pragma unroll
        for (int i = 0; i < 2; i++) {
            int id = tid + i * 256;
            int pl = id >> 8, r = (id >> 2) & 63, c = id & 3;
            const __half* Wp = pl ? Wi : Wr;
            unsigned off = 2 * PASZ + (pl * 2 + buf) * PBSZ;
            cpa16(sbase + (off + (unsigned)(r * PA_S)) * 2u + c * 16,
                  Wp + (size_t)(n0 + r) * HIDC + ko + c * 8);
        }
        cpcommit();
    };

    issue(0);
    issue(1);

    for (int it = 0; it < 64; it++) {
        if (it < 63) cpwait1(); else cpwait0();
        __syncthreads();

        int buf = it & 1;
        bool ph2 = (it >= 32);
        const __half* Ab = sm + buf * PASZ;
        const __half* Bb = sm + 2 * PASZ + buf * PBSZ;

#pragma unroll
        for (int ks = 0; ks < 2; ks++) {
            unsigned af[2][4];
#pragma unroll
            for (int mt = 0; mt < 2; mt++) {
                const __half* ap = Ab + (wm * 32 + mt * 16 + g) * PA_S + ks * 16 + t4 * 4;
                uint2 lo = *reinterpret_cast<const uint2*>(ap);
                uint2 hi = *reinterpret_cast<const uint2*>(ap + 8 * PA_S);
                af[mt][0] = lo.x; af[mt][1] = hi.x; af[mt][2] = lo.y; af[mt][3] = hi.y;
            }
            unsigned naf[2][4];
            if (ph2) {
#pragma unroll
                for (int mt = 0; mt < 2; mt++)
#pragma unroll
                    for (int q = 0; q < 4; q++) naf[mt][q] = af[mt][q] ^ 0x80008000u;
            }
#pragma unroll
            for (int nt = 0; nt < 4; nt++) {
                const __half* bp = Bb + (wn * 32 + nt * 8 + g) * PA_S + ks * 16 + t4 * 4;
                uint2 bR = *reinterpret_cast<const uint2*>(bp);
                uint2 bI = *reinterpret_cast<const uint2*>(bp + 2 * PBSZ);
                if (ph2) {
#pragma unroll
                    for (int mt = 0; mt < 2; mt++) {
                        mmaf16(accR[mt][nt], naf[mt][0], naf[mt][1], naf[mt][2], naf[mt][3], bI.x, bI.y);
                        mmaf16(accI[mt][nt], af[mt][0], af[mt][1], af[mt][2], af[mt][3], bR.x, bR.y);
                    }
                } else {
#pragma unroll
                    for (int mt = 0; mt < 2; mt++) {
                        mmaf16(accR[mt][nt], af[mt][0], af[mt][1], af[mt][2], af[mt][3], bR.x, bR.y);
                        mmaf16(accI[mt][nt], af[mt][0], af[mt][1], af[mt][2], af[mt][3], bI.x, bI.y);
                    }
                }
            }
        }
        __syncthreads();
        if (it + 2 < 64) issue(it + 2);
    }

    // epilogue (mode-dispatched, block-uniform)
#pragma unroll
    for (int mt = 0; mt < 2; mt++) {
#pragma unroll
        for (int hrw = 0; hrw < 2; hrw++) {
            int r = m0 + wm * 32 + mt * 16 + g + hrw * 8;
            int bq = r >> 10, tk = r & 1023;
#pragma unroll
            for (int nt = 0; nt < 4; nt++) {
                int c0 = n0 + wn * 32 + nt * 8 + 2 * t4;
                float vr0 = accR[mt][nt][hrw * 2 + 0] + brp[c0];
                float vr1 = accR[mt][nt][hrw * 2 + 1] + brp[c0 + 1];
                float vi0 = accI[mt][nt][hrw * 2 + 0] + bip[c0];
                float vi1 = accI[mt][nt][hrw * 2 + 1] + bip[c0 + 1];
                int h = c0 >> 6, d = c0 & 63;
                int s = (d & ~15) + slot16(d & 15);

                if (mode == 0) {
                    size_t base = ((size_t)(bq * 16 + h) * 1024 + tk) * 128;
                    *reinterpret_cast<__half2*>(qh + base + s) = __floats2half2_rn(vr0, vr1);
                    *reinterpret_cast<__half2*>(qh + base + 64 + s) = __floats2half2_rn(vi0, vi1);
                } else if (mode == 1) {
                    size_t orow = (size_t)bq * TKV + CACHE + tk;
                    nKr[orow * HIDC + c0] = vr0;  nKr[orow * HIDC + c0 + 1] = vr1;
                    nKi[orow * HIDC + c0] = vi0;  nKi[orow * HIDC + c0 + 1] = vi1;
                    size_t base = ((size_t)(bq * 16 + h) * 4096 + CACHE + tk) * 128;
                    *reinterpret_cast<__half2*>(kh + base + s) = __floats2half2_rn(vr0, vr1);
                    *reinterpret_cast<__half2*>(kh + base + 64 + s) = __floats2half2_rn(vi0, vi1);
                } else {
                    size_t orow = (size_t)bq * TKV + CACHE + tk;
                    nVr[orow * HIDC + c0] = vr0;  nVr[orow * HIDC + c0 + 1] = vr1;
                    nVi[orow * HIDC + c0] = vi0;  nVi[orow * HIDC + c0 + 1] = vi1;
                }
            }
        }
    }
}

// ---------------- O projection (fp32 out + residual) ----------------
__global__ void __launch_bounds__(256, 2)
oproj_kernel(const __half* __restrict__ A1, const __half* __restrict__ A2,
             const __half* __restrict__ Wr, const __half* __restrict__ Wi,
             const float* __restrict__ brp, const float* __restrict__ bip,
             float* __restrict__ Or, float* __restrict__ Oi,
             const float* __restrict__ Rr, const float* __restrict__ Ri) {
    __shared__ __half sm[2 * PASZ + 4 * PBSZ];
    unsigned sbase = (unsigned)__cvta_generic_to_shared(sm);

    int tid = threadIdx.x, lane = tid & 31, wid = tid >> 5;
    int wm = wid & 3, wn = wid >> 2;
    int g = lane >> 2, t4 = lane & 3;
    int n0 = blockIdx.x * 64;
    int m0 = blockIdx.y * 128;

    float accR[2][4][4];
    float accI[2][4][4];
#pragma unroll
    for (int a = 0; a < 2; a++)
#pragma unroll
        for (int b = 0; b < 4; b++)
#pragma unroll
            for (int c = 0; c < 4; c++) { accR[a][b][c] = 0.f; accI[a][b][c] = 0.f; }

    auto issue = [&](int it) {
        bool ph2 = it >= 32;
        int ko = it * 32 - (ph2 ? 1024 : 0);
        const __half* Ap = ph2 ? A2 : A1;
        int buf = it & 1;
#pragma unroll
        for (int i = 0; i < 2; i++) {
            int id = tid + i * 256;
            int r = id >> 2, c = id & 3;
            cpa16(sbase + (unsigned)(buf * PASZ + r * PA_S) * 2u + c * 16,
                  Ap + (size_t)(m0 + r) * HIDC + ko + c * 8);
        }
#pragma unroll
        for (int i = 0; i < 2; i++) {
            int id = tid + i * 256;
            int pl = id >> 8, r = (id >> 2) & 63, c = id & 3;
            const __half* Wp = pl ? Wi : Wr;
            unsigned off = 2 * PASZ + (pl * 2 + buf) * PBSZ;
            cpa16(sbase + (off + (unsigned)(r * PA_S)) * 2u + c * 16,
                  Wp + (size_t)(n0 + r) * HIDC + ko + c * 8);
        }
        cpcommit();
    };

    issue(0);
    issue(1);

    for (int it = 0; it < 64; it++) {
        if (it < 63) cpwait1(); else cpwait0();
        __syncthreads();

        int buf = it & 1;
        bool ph2 = (it >= 32);
        const __half* Ab = sm + buf * PASZ;
        const __half* Bb = sm + 2 * PASZ + buf * PBSZ;

#pragma unroll
        for (int ks = 0; ks < 2; ks++) {
            unsigned af[2][4];
#pragma unroll
            for (int mt = 0; mt < 2; mt++) {
                const __half* ap = Ab + (wm * 32 + mt * 16 + g) * PA_S + ks * 16 + t4 * 4;
                uint2 lo = *reinterpret_cast<const uint2*>(ap);
                uint2 hi = *reinterpret_cast<const uint2*>(ap + 8 * PA_S);
                af[mt][0] = lo.x; af[mt][1] = hi.x; af[mt][2] = lo.y; af[mt][3] = hi.y;
            }
            unsigned naf[2][4];
            if (ph2) {
#pragma unroll
                for (int mt = 0; mt < 2; mt++)
#pragma unroll
                    for (int q = 0; q < 4; q++) naf[mt][q] = af[mt][q] ^ 0x80008000u;
            }
#pragma unroll
            for (int nt = 0; nt < 4; nt++) {
                const __half* bp = Bb + (wn * 32 + nt * 8 + g) * PA_S + ks * 16 + t4 * 4;
                uint2 bR = *reinterpret_cast<const uint2*>(bp);
                uint2 bI = *reinterpret_cast<const uint2*>(bp + 2 * PBSZ);
                if (ph2) {
#pragma unroll
                    for (int mt = 0; mt < 2; mt++) {
                        mmaf16(accR[mt][nt], naf[mt][0], naf[mt][1], naf[mt][2], naf[mt][3], bI.x, bI.y);
                        mmaf16(accI[mt][nt], af[mt][0], af[mt][1], af[mt][2], af[mt][3], bR.x, bR.y);
                    }
                } else {
#pragma unroll
                    for (int mt = 0; mt < 2; mt++) {
                        mmaf16(accR[mt][nt], af[mt][0], af[mt][1], af[mt][2], af[mt][3], bR.x, bR.y);
                        mmaf16(accI[mt][nt], af[mt][0], af[mt][1], af[mt][2], af[mt][3], bI.x, bI.y);
                    }
                }
            }
        }
        __syncthreads();
        if (it + 2 < 64) issue(it + 2);
    }

#pragma unroll
    for (int mt = 0; mt < 2; mt++) {
#pragma unroll
        for (int hrw = 0; hrw < 2; hrw++) {
            int r = m0 + wm * 32 + mt * 16 + g + hrw * 8;
#pragma unroll
            for (int nt = 0; nt < 4; nt++) {
                int c0 = n0 + wn * 32 + nt * 8 + 2 * t4;
                float vr0 = accR[mt][nt][hrw * 2 + 0] + brp[c0];
                float vr1 = accR[mt][nt][hrw * 2 + 1] + brp[c0 + 1];
                float vi0 = accI[mt][nt][hrw * 2 + 0] + bip[c0];
                float vi1 = accI[mt][nt][hrw * 2 + 1] + bip[c0 + 1];
                size_t rowo = (size_t)r * HIDC;
                Or[rowo + c0]     = vr0 + Rr[rowo + c0];
                Or[rowo + c0 + 1] = vr1 + Rr[rowo + c0 + 1];
                Oi[rowo + c0]     = vi0 + Ri[rowo + c0];
                Oi[rowo + c0 + 1] = vi1 + Ri[rowo + c0 + 1];
            }
        }
    }
}

// ---------------- Flash attention (fp16 mma, occ 1, balanced pairs — R11) ----------------
constexpr int AQ_S = 136;                 // halves
constexpr int AK_S = 136;
constexpr int AV_S = 72;                  // V^T rows (64 kv + 8 pad)
constexpr int Q_SZ = 128 * AQ_S;          // 17408 halves
constexpr int K_SZ = 64 * AK_S;           // 8704
constexpr int V_SZ = 128 * AV_S;          // 9216
constexpr int AT_SMEM = (Q_SZ + 2 * K_SZ + 2 * V_SZ) * 2;   // 106496 bytes

__global__ void __launch_bounds__(256, 1)
attn_kernel(const __half* __restrict__ Qp, const __half* __restrict__ Kp,
            const __half* __restrict__ Vp,
            __half* __restrict__ ar, __half* __restrict__ ai) {
    extern __shared__ __half smh[];
    __half* Qs = smh;
    unsigned sbase = (unsigned)__cvta_generic_to_shared(smh);

    int tid = threadIdx.x, lane = tid & 31, wid = tid >> 5;
    int g = lane >> 2, t4 = lane & 3;
    int bh = blockIdx.x >> 2;
    int p  = blockIdx.x & 3;
    int b = bh >> 4, h = bh & 15;
    int wq = wid * 16;

    for (int rep = 0; rep < 2; rep++) {
        int qb = rep ? (7 - p) : p;
        int q0 = qb * 128;
        int t_end = min(TKV, q0 + 3200);
        int nIter = t_end / 64;

#pragma unroll
        for (int i = 0; i < 8; i++) {
            int id = tid + i * 256;
            int r = id >> 4, c = id & 15;
            cpa16(sbase + (unsigned)(r * AQ_S) * 2u + c * 16,
                  Qp + ((size_t)bh * 1024 + q0 + r) * 128 + c * 8);
        }

        auto issueKV = [&](int it) {
            int t0 = it * 64;
            int buf = it & 1;
            unsigned kb0 = (unsigned)(Q_SZ + buf * K_SZ) * 2u;
            unsigned vb0 = (unsigned)(Q_SZ + 2 * K_SZ + buf * V_SZ) * 2u;
#pragma unroll
            for (int i = 0; i < 4; i++) {
                int id = tid + i * 256;
                int r = id >> 4, c = id & 15;
                cpa16(kb0 + sbase + (unsigned)(r * AK_S) * 2u + c * 16,
                      Kp + ((size_t)bh * 4096 + t0 + r) * 128 + c * 8);
            }
#pragma unroll
            for (int i = 0; i < 4; i++) {
                int id = tid + i * 256;
                int r = id >> 3, c = id & 7;
                cpa16(vb0 + sbase + (unsigned)(r * AV_S) * 2u + c * 16,
                      Vp + ((size_t)bh * 128 + r) * 4096 + t0 + c * 8);
            }
            cpcommit();
        };

        issueKV(0);
        issueKV(1);

        float mrow[2] = { -1e30f, -1e30f };
        float lrow[2] = { 0.f, 0.f };
        float o[16][4];
#pragma unroll
        for (int nt = 0; nt < 16; nt++) { o[nt][0] = o[nt][1] = o[nt][2] = o[nt][3] = 0.f; }

        for (int it = 0; it < nIter; it++) {
            if (it + 1 < nIter) cpwait1(); else cpwait0();
            __syncthreads();

            int t0 = it * 64;
            int buf = it & 1;
            const __half* Kb = smh + Q_SZ + buf * K_SZ;
            const __half* Vb = smh + Q_SZ + 2 * K_SZ + buf * V_SZ;

            float s[8][4];
#pragma unroll
            for (int nt = 0; nt < 8; nt++) { s[nt][0] = s[nt][1] = s[nt][2] = s[nt][3] = 0.f; }
#pragma unroll
            for (int ks = 0; ks < 8; ks++) {
                const __half* ap = Qs + (wq + g) * AQ_S + ks * 16 + t4 * 4;
                uint2 lo = *reinterpret_cast<const uint2*>(ap);
                uint2 hi = *reinterpret_cast<const uint2*>(ap + 8 * AQ_S);
                unsigned a0 = lo.x, a1 = hi.x, a2 = lo.y, a3 = hi.y;
#pragma unroll
                for (int nt = 0; nt < 8; nt++) {
                    uint2 bb = *reinterpret_cast<const uint2*>(
                        Kb + (nt * 8 + g) * AK_S + ks * 16 + t4 * 4);
                    mmaf16(s[nt], a0, a1, a2, a3, bb.x, bb.y);
                }
            }

            bool needmask = (t0 + 63 > q0 + CACHE);
            int rg0 = q0 + wq + g, rg1 = rg0 + 8;
#pragma unroll
            for (int nt = 0; nt < 8; nt++) {
                s[nt][0] *= 0.125f; s[nt][1] *= 0.125f; s[nt][2] *= 0.125f; s[nt][3] *= 0.125f;
                if (needmask) {
                    int c0 = t0 + nt * 8 + 2 * t4;
                    if (c0     > rg0 + CACHE) s[nt][0] = -1e30f;
                    if (c0 + 1 > rg0 + CACHE) s[nt][1] = -1e30f;
                    if (c0     > rg1 + CACHE) s[nt][2] = -1e30f;
                    if (c0 + 1 > rg1 + CACHE) s[nt][3] = -1e30f;
                }
            }

            float mx0 = -1e30f, mx1 = -1e30f;
#pragma unroll
            for (int nt = 0; nt < 8; nt++) {
                mx0 = fmaxf(mx0, fmaxf(s[nt][0], s[nt][1]));
                mx1 = fmaxf(mx1, fmaxf(s[nt][2], s[nt][3]));
            }
            mx0 = fmaxf(mx0, __shfl_xor_sync(0xffffffffu, mx0, 1));
            mx0 = fmaxf(mx0, __shfl_xor_sync(0xffffffffu, mx0, 2));
            mx1 = fmaxf(mx1, __shfl_xor_sync(0xffffffffu, mx1, 1));
            mx1 = fmaxf(mx1, __shfl_xor_sync(0xffffffffu, mx1, 2));
            float mn0 = fmaxf(mrow[0], mx0), mn1 = fmaxf(mrow[1], mx1);
            float al0 = __expf(mrow[0] - mn0), al1 = __expf(mrow[1] - mn1);
            float rs0 = 0.f, rs1 = 0.f;
#pragma unroll
            for (int nt = 0; nt < 8; nt++) {
                s[nt][0] = __expf(s[nt][0] - mn0);
                s[nt][1] = __expf(s[nt][1] - mn0);
                s[nt][2] = __expf(s[nt][2] - mn1);
                s[nt][3] = __expf(s[nt][3] - mn1);
                rs0 += s[nt][0] + s[nt][1];
                rs1 += s[nt][2] + s[nt][3];
            }
            rs0 += __shfl_xor_sync(0xffffffffu, rs0, 1);
            rs0 += __shfl_xor_sync(0xffffffffu, rs0, 2);
            rs1 += __shfl_xor_sync(0xffffffffu, rs1, 1);
            rs1 += __shfl_xor_sync(0xffffffffu, rs1, 2);
            lrow[0] = lrow[0] * al0 + rs0;
            lrow[1] = lrow[1] * al1 + rs1;
            mrow[0] = mn0; mrow[1] = mn1;
#pragma unroll
            for (int nt = 0; nt < 16; nt++) {
                o[nt][0] *= al0; o[nt][1] *= al0; o[nt][2] *= al1; o[nt][3] *= al1;
            }

#pragma unroll
            for (int kb = 0; kb < 4; kb++) {
                unsigned a0 = packh2(s[2 * kb][0], s[2 * kb][1]);
                unsigned a1 = packh2(s[2 * kb][2], s[2 * kb][3]);
                unsigned a2 = packh2(s[2 * kb + 1][0], s[2 * kb + 1][1]);
                unsigned a3 = packh2(s[2 * kb + 1][2], s[2 * kb + 1][3]);
#pragma unroll
                for (int nt = 0; nt < 16; nt++) {
                    const __half* vp = Vb + (nt * 8 + g) * AV_S + kb * 16 + 2 * t4;
                    unsigned b0 = *reinterpret_cast<const unsigned*>(vp);
                    unsigned b1 = *reinterpret_cast<const unsigned*>(vp + 8);
                    mmaf16(o[nt], a0, a1, a2, a3, b0, b1);
                }
            }
            __syncthreads();
            if (it + 2 < nIter) issueKV(it + 2);
        }

        // epilogue — fp16 perm16 planes for the O-projection
        float il0 = 1.0f / lrow[0], il1 = 1.0f / lrow[1];
        int r0 = q0 + wq + g;
        size_t rb0 = (size_t)(b * SEQ + r0) * HIDC;
        size_t rb1 = rb0 + (size_t)8 * HIDC;
#pragma unroll
        for (int nt = 0; nt < 16; nt++) {
            int d0 = nt * 8 + 2 * t4;
            __half* dst = (d0 < 64) ? ar : ai;
            int dd = d0 & 63;
            int hid = h * 64 + dd;
            int s = (hid & ~15) + slot16(hid & 15);
            *reinterpret_cast<__half2*>(dst + rb0 + s) =
                __floats2half2_rn(o[nt][0] * il0, o[nt][1] * il0);
            *reinterpret_cast<__half2*>(dst + rb1 + s) =
                __floats2half2_rn(o[nt][2] * il1, o[nt][3] * il1);
        }
    }
}

// ---------------- launcher (forked-stream schedule) ----------------
extern "C" void kernel_launch(void* const* d_in, const int* in_sizes, int n_in,
                              void* d_out, int out_size) {
    const float* hr    = (const float*)d_in[0];
    const float* hi    = (const float*)d_in[1];
    const float* Kcr   = (const float*)d_in[2];
    const float* Kci   = (const float*)d_in[3];
    const float* Vcr   = (const float*)d_in[4];
    const float* Vci   = (const float*)d_in[5];
    const float* gamma = (const float*)d_in[6];
    const float* betar = (const float*)d_in[7];
    const float* betai = (const float*)d_in[8];
    const float* qbr = (const float*)d_in[11], *qbi = (const float*)d_in[12];
    const float* kbr = (const float*)d_in[15], *kbi = (const float*)d_in[16];
    const float* vbr = (const float*)d_in[19], *vbi = (const float*)d_in[20];
    const float* obr = (const float*)d_in[23], *obi = (const float*)d_in[24];

    float* out = (float*)d_out;
    float* outR = out + OFF_OUT_RE;
    float* outI = out + OFF_OUT_IM;
    float* nKr  = out + OFF_K_RE;
    float* nKi  = out + OFF_K_IM;
    float* nVr  = out + OFF_V_RE;
    float* nVi  = out + OFF_V_IM;

    __half *nrh, *nih, *arh, *aih, *qh, *kh, *vt, *wh;
    cudaGetSymbolAddress((void**)&nrh, g_nrh);
    cudaGetSymbolAddress((void**)&nih, g_nih);
    cudaGetSymbolAddress((void**)&arh, g_arh);
    cudaGetSymbolAddress((void**)&aih, g_aih);
    cudaGetSymbolAddress((void**)&qh, g_qh);
    cudaGetSymbolAddress((void**)&kh, g_kh);
    cudaGetSymbolAddress((void**)&vt, g_vt);
    cudaGetSymbolAddress((void**)&wh, g_wh);

    cudaFuncSetAttribute(attn_kernel, cudaFuncAttributeMaxDynamicSharedMemorySize, AT_SMEM);

    // one-time stream/event setup (first call is the uncaptured correctness run)
    static cudaStream_t sB = nullptr, sC = nullptr;
    static cudaEvent_t e0 = nullptr, eB = nullptr, eC = nullptr;
    if (!sB) {
        cudaStreamCreateWithFlags(&sB, cudaStreamNonBlocking);
        cudaStreamCreateWithFlags(&sC, cudaStreamNonBlocking);
        cudaEventCreateWithFlags(&e0, cudaEventDisableTiming);
        cudaEventCreateWithFlags(&eB, cudaEventDisableTiming);
        cudaEventCreateWithFlags(&eC, cudaEventDisableTiming);
    }

    // fork point
    cudaEventRecord(e0, 0);

    // stream B: weight convert (independent of LN)
    cudaStreamWaitEvent(sB, e0, 0);
    wconv_kernel<<<(int)((8u * 1024 * 1024) / 256), 256, 0, sB>>>(
        (const float*)d_in[9],  (const float*)d_in[10],
        (const float*)d_in[13], (const float*)d_in[14],
        (const float*)d_in[17], (const float*)d_in[18],
        (const float*)d_in[21], (const float*)d_in[22], wh);
    cudaEventRecord(eB, sB);

    // stream C: fp32 cache copies + K-cache fp16 conversion (overlap with qkv)
    cudaStreamWaitEvent(sC, e0, 0);
    for (int b = 0; b < NBAT; b++) {
        size_t dofs = (size_t)b * TKV * HIDC;
        size_t sofs = (size_t)b * CACHE * HIDC;
        size_t bytes = (size_t)CACHE * HIDC * sizeof(float);
        cudaMemcpyAsync(nKr + dofs, Kcr + sofs, bytes, cudaMemcpyDeviceToDevice, sC);
        cudaMemcpyAsync(nKi + dofs, Kci + sofs, bytes, cudaMemcpyDeviceToDevice, sC);
        cudaMemcpyAsync(nVr + dofs, Vcr + sofs, bytes, cudaMemcpyDeviceToDevice, sC);
        cudaMemcpyAsync(nVi + dofs, Vci + sofs, bytes, cudaMemcpyDeviceToDevice, sC);
    }
    kcache_conv<<<(int)((2u * 3072 * 1024) / 256), 256, 0, sC>>>(Kcr, Kci, kh);
    cudaEventRecord(eC, sC);

    // main stream: LN (overlaps wconv), then qkv (overlaps copies)
    ln_kernel<<<MTOT, 256>>>(hr, hi, gamma, betar, betai, nrh, nih);

    cudaStreamWaitEvent(0, eB, 0);
    qkv_kernel<<<dim3(HIDC / 64, MTOT / 128, 3), 256>>>(
        nrh, nih, wh, qbr, qbi, kbr, kbi, vbr, vbi,
        nKr, nKi, nVr, nVi, qh, kh);

    // join memory stream before vtrans/attn (need V cache fp32 + K fp16 cache plane)
    cudaStreamWaitEvent(0, eC, 0);
    vtrans_kernel<<<dim3(64, 32), 256>>>(nVr, nVi, vt);

    attn_kernel<<<128, 256, AT_SMEM>>>(qh, kh, vt, arh, aih);

    constexpr size_t WPL = 1024u * 1024u;
    oproj_kernel<<<dim3(HIDC / 64, MTOT / 128), 256>>>(
        arh, aih, wh + 6 * WPL, wh + 7 * WPL, obr, obi, outR, outI, hr, hi);
}

// round 16
// speedup vs baseline: 1.1633x; 1.0639x over previous
#include <cuda_runtime.h>
#include <cuda_fp16.h>
#include <cstdint>
#include <cstddef>

// Problem constants
constexpr int HIDC  = 1024;
constexpr int SEQ   = 1024;
constexpr int NBAT  = 2;
constexpr int CACHE = 3072;
constexpr int TKV   = 4096;
constexpr int MTOT  = NBAT * SEQ;               // 2048 rows
constexpr size_t PLANE = (size_t)MTOT * HIDC;   // 2,097,152

// Output offsets (floats)
constexpr size_t OFF_OUT_RE = 0;
constexpr size_t OFF_OUT_IM = 2097152;
constexpr size_t OFF_K_RE   = 4194304;
constexpr size_t OFF_K_IM   = 12582912;
constexpr size_t OFF_V_RE   = 20971520;
constexpr size_t OFF_V_IM   = 29360128;

// Scratch (device globals — allocation-free)
__device__ __half g_nrh[PLANE];                  // LN out (fp16, perm16 over k)
__device__ __half g_nih[PLANE];
__device__ __half g_arh[PLANE];                  // attn out (fp16, perm16 over hid)
__device__ __half g_aih[PLANE];
__device__ __half g_qh[(size_t)32 * 1024 * 128]; // Q plane [bh][tok][128] perm16
__device__ __half g_kh[(size_t)32 * 4096 * 128]; // K plane [bh][tok][128] perm16
__device__ __half g_vt[(size_t)32 * 128 * 4096]; // V^T plane [bh][dim][tok]
__device__ __half g_wh[(size_t)8 * 1024 * 1024]; // weights fp16 perm16

// ---------------- helpers ----------------
__device__ __forceinline__ unsigned u32(float x) { return __float_as_uint(x); }

// perm16: reorder each 16-element k-group so a thread's fp16 A/B fragment
// (k = {2t4, 2t4+1, 2t4+8, 2t4+9}) is 4 contiguous halves.
__device__ __forceinline__ int slot16(int w) {
    return ((w >> 1) & 3) * 4 + ((w >> 3) & 1) * 2 + (w & 1);
}
__device__ __forceinline__ int permidx(int k) { return (k & ~15) + slot16(k & 15); }

__device__ __forceinline__ unsigned packh2(float x, float y) {
    __half2 h = __floats2half2_rn(x, y);
    return *reinterpret_cast<unsigned*>(&h);
}

__device__ __forceinline__ void mmaf16(float* c, unsigned a0, unsigned a1, unsigned a2,
                                       unsigned a3, unsigned b0, unsigned b1) {
    asm("mma.sync.aligned.m16n8k16.row.col.f32.f16.f16.f32 "
        "{%0,%1,%2,%3},{%4,%5,%6,%7},{%8,%9},{%0,%1,%2,%3};"
        : "+f"(c[0]), "+f"(c[1]), "+f"(c[2]), "+f"(c[3])
        : "r"(a0), "r"(a1), "r"(a2), "r"(a3), "r"(b0), "r"(b1));
}

__device__ __forceinline__ void cpa16(unsigned dst, const void* src) {
    asm volatile("cp.async.cg.shared.global [%0], [%1], 16;" :: "r"(dst), "l"(src) : "memory");
}
__device__ __forceinline__ void cpcommit() { asm volatile("cp.async.commit_group;" ::: "memory"); }
__device__ __forceinline__ void cpwait0() { asm volatile("cp.async.wait_group 0;" ::: "memory"); }
__device__ __forceinline__ void cpwait1() { asm volatile("cp.async.wait_group 1;" ::: "memory"); }
__device__ __forceinline__ void cpwait2() { asm volatile("cp.async.wait_group 2;" ::: "memory"); }

// ---------------- weight convert: fp32 -> fp16 perm16 (sector-coalesced) ----------------
__global__ void wconv_kernel(const float* s0, const float* s1, const float* s2, const float* s3,
                             const float* s4, const float* s5, const float* s6, const float* s7,
                             __half* dst) {
    size_t i = (size_t)blockIdx.x * blockDim.x + threadIdx.x;   // 8M threads
    int p = (int)(i >> 20);
    size_t w = i & 1048575u;
    const float* sp;
    switch (p) {
        case 0: sp = s0; break; case 1: sp = s1; break;
        case 2: sp = s2; break; case 3: sp = s3; break;
        case 4: sp = s4; break; case 5: sp = s5; break;
        case 6: sp = s6; break; default: sp = s7; break;
    }
    int k = (int)(w & 1023);
    dst[(i & ~(size_t)1023) + permidx(k)] = __float2half(sp[w]);
}

// ---------------- K cache convert: fp32 [b][t][h][64] -> K plane (perm16) ----------------
__global__ void kcache_conv(const float* __restrict__ re, const float* __restrict__ im,
                            __half* __restrict__ Kh) {
    size_t i = (size_t)blockIdx.x * blockDim.x + threadIdx.x;   // 2*3072*1024
    int hd = (int)(i & 1023);
    int t  = (int)((i >> 10) % 3072u);
    int b  = (int)(i / (3072u * 1024u));
    int h = hd >> 6, d = hd & 63;
    size_t base = ((size_t)(b * 16 + h) * 4096 + t) * 128;
    int s = (d & ~15) + slot16(d & 15);
    Kh[base + s]      = __float2half(re[i]);
    Kh[base + 64 + s] = __float2half(im[i]);
}

// ---------------- V transpose (parameterized): fp32 V -> fp16 V^T [bh][dim 128][tok] ----------------
// srcStride = tokens per batch in src; dstOff = token offset in V^T plane.
__global__ void vtrans_kernel(const float* __restrict__ Vr, const float* __restrict__ Vi,
                              __half* __restrict__ Vt, int srcStride, int srcOff, int dstOff) {
    __shared__ float Tr[64][65];
    __shared__ float Ti[64][65];
    int tt = blockIdx.x;            // 64-token tile within this region
    int bh = blockIdx.y;            // 0..31
    int b = bh >> 4, h = bh & 15;
    int t0 = tt * 64;
    int tid = threadIdx.x;
#pragma unroll
    for (int i = 0; i < 16; i++) {
        int id = tid + i * 256;
        int tok = id >> 6, d = id & 63;
        size_t src = ((size_t)b * srcStride + srcOff + t0 + tok) * HIDC + h * 64 + d;
        Tr[tok][d] = Vr[src];
        Ti[tok][d] = Vi[src];
    }
    __syncthreads();
#pragma unroll
    for (int i = 0; i < 32; i++) {
        int id = tid + i * 256;
        int dim = id >> 6, tok = id & 63;
        float v = (dim < 64) ? Tr[tok][dim] : Ti[tok][dim - 64];
        Vt[((size_t)bh * 128 + dim) * 4096 + dstOff + t0 + tok] = __float2half(v);
    }
}

// ---------------- Complex LayerNorm -> fp16 perm16 planes ----------------
__global__ void ln_kernel(const float* __restrict__ hr, const float* __restrict__ hi,
                          const float* __restrict__ gamma,
                          const float* __restrict__ betar, const float* __restrict__ betai,
                          __half* __restrict__ nr, __half* __restrict__ ni) {
    int row = blockIdx.x;
    int tid = threadIdx.x, lane = tid & 31, wid = tid >> 5;
    const float* pr = hr + (size_t)row * HIDC;
    const float* pi = hi + (size_t)row * HIDC;

    float vr[4], vi[4];
    float sr = 0.f, si = 0.f, sq = 0.f;
#pragma unroll
    for (int j = 0; j < 4; j++) {
        int e = tid + j * 256;
        vr[j] = pr[e]; vi[j] = pi[e];
        sr += vr[j]; si += vi[j]; sq += vr[j] * vr[j] + vi[j] * vi[j];
    }
#pragma unroll
    for (int o = 16; o; o >>= 1) {
        sr += __shfl_xor_sync(0xffffffffu, sr, o);
        si += __shfl_xor_sync(0xffffffffu, si, o);
        sq += __shfl_xor_sync(0xffffffffu, sq, o);
    }
    __shared__ float red[3][8];
    if (lane == 0) { red[0][wid] = sr; red[1][wid] = si; red[2][wid] = sq; }
    __syncthreads();
    float tsr = 0.f, tsi = 0.f, tsq = 0.f;
#pragma unroll
    for (int w = 0; w < 8; w++) { tsr += red[0][w]; tsi += red[1][w]; tsq += red[2][w]; }
    float mur = tsr * (1.0f / HIDC);
    float mui = tsi * (1.0f / HIDC);
    float var = tsq * (1.0f / HIDC) - mur * mur - mui * mui;
    float inv = rsqrtf(var + 1e-5f);
#pragma unroll
    for (int j = 0; j < 4; j++) {
        int e = tid + j * 256;
        float gm = gamma[e] * inv;
        int pe = permidx(e);
        nr[(size_t)row * HIDC + pe] = __float2half((vr[j] - mur) * gm + betar[e]);
        ni[(size_t)row * HIDC + pe] = __float2half((vi[j] - mui) * gm + betai[e]);
    }
}

// ---------------- Projection GEMM shapes (4-stage pipeline) ----------------
constexpr int PA_S   = 40;                  // row stride in halves (80 B)
constexpr int PASZ   = 128 * PA_S;          // 5120 halves (A tile)
constexpr int PBSZ   = 64 * PA_S;           // 2560 halves (one B plane)
constexpr int STG_H  = PASZ + 2 * PBSZ;     // 10240 halves per stage
constexpr int PJ_SMEM = 4 * STG_H * 2;      // 81920 bytes

// ---------------- Merged Q/K/V projection (one launch, mode = blockIdx.z) ----------------
// mode 0: Q -> fp16 Q plane; mode 1: K -> fp32 kv + fp16 K plane; mode 2: V -> fp32 kv.
__global__ void __launch_bounds__(256, 2)
qkv_kernel(const __half* __restrict__ A1, const __half* __restrict__ A2,
           const __half* __restrict__ WH,
           const float* __restrict__ qbr, const float* __restrict__ qbi,
           const float* __restrict__ kbr, const float* __restrict__ kbi,
           const float* __restrict__ vbr, const float* __restrict__ vbi,
           float* __restrict__ nKr, float* __restrict__ nKi,
           float* __restrict__ nVr, float* __restrict__ nVi,
           __half* __restrict__ qh, __half* __restrict__ kh) {
    extern __shared__ __half sm[];
    unsigned sbase = (unsigned)__cvta_generic_to_shared(sm);

    int mode = blockIdx.z;
    const __half* Wr = WH + ((size_t)(2 * mode) << 20);
    const __half* Wi = Wr + ((size_t)1 << 20);
    const float* brp = (mode == 0) ? qbr : (mode == 1) ? kbr : vbr;
    const float* bip = (mode == 0) ? qbi : (mode == 1) ? kbi : vbi;

    int tid = threadIdx.x, lane = tid & 31, wid = tid >> 5;
    int wm = wid & 3, wn = wid >> 2;
    int g = lane >> 2, t4 = lane & 3;
    int n0 = blockIdx.x * 64;
    int m0 = blockIdx.y * 128;

    float accR[2][4][4];
    float accI[2][4][4];
#pragma unroll
    for (int a = 0; a < 2; a++)
#pragma unroll
        for (int b = 0; b < 4; b++)
#pragma unroll
            for (int c = 0; c < 4; c++) { accR[a][b][c] = 0.f; accI[a][b][c] = 0.f; }

    auto issue = [&](int it) {
        bool ph2 = it >= 32;
        int ko = it * 32 - (ph2 ? 1024 : 0);
        const __half* Ap = ph2 ? A2 : A1;
        unsigned stg = (unsigned)(it & 3) * STG_H;
#pragma unroll
        for (int i = 0; i < 2; i++) {
            int id = tid + i * 256;
            int r = id >> 2, c = id & 3;
            cpa16(sbase + (stg + (unsigned)(r * PA_S)) * 2u + c * 16,
                  Ap + (size_t)(m0 + r) * HIDC + ko + c * 8);
        }
#pragma unroll
        for (int i = 0; i < 2; i++) {
            int id = tid + i * 256;
            int pl = id >> 8, r = (id >> 2) & 63, c = id & 3;
            const __half* Wp = pl ? Wi : Wr;
            unsigned off = stg + PASZ + (unsigned)pl * PBSZ;
            cpa16(sbase + (off + (unsigned)(r * PA_S)) * 2u + c * 16,
                  Wp + (size_t)(n0 + r) * HIDC + ko + c * 8);
        }
        cpcommit();
    };

    issue(0);
    issue(1);
    issue(2);

    for (int it = 0; it < 64; it++) {
        if (it < 62) cpwait2(); else if (it == 62) cpwait1(); else cpwait0();
        __syncthreads();

        bool ph2 = (it >= 32);
        const __half* Ab = sm + (it & 3) * STG_H;
        const __half* Bb = Ab + PASZ;

#pragma unroll
        for (int ks = 0; ks < 2; ks++) {
            unsigned af[2][4];
#pragma unroll
            for (int mt = 0; mt < 2; mt++) {
                const __half* ap = Ab + (wm * 32 + mt * 16 + g) * PA_S + ks * 16 + t4 * 4;
                uint2 lo = *reinterpret_cast<const uint2*>(ap);
                uint2 hi = *reinterpret_cast<const uint2*>(ap + 8 * PA_S);
                af[mt][0] = lo.x; af[mt][1] = hi.x; af[mt][2] = lo.y; af[mt][3] = hi.y;
            }
            unsigned naf[2][4];
            if (ph2) {
#pragma unroll
                for (int mt = 0; mt < 2; mt++)
#pragma unroll
                    for (int q = 0; q < 4; q++) naf[mt][q] = af[mt][q] ^ 0x80008000u;
            }
#pragma unroll
            for (int nt = 0; nt < 4; nt++) {
                const __half* bp = Bb + (wn * 32 + nt * 8 + g) * PA_S + ks * 16 + t4 * 4;
                uint2 bR = *reinterpret_cast<const uint2*>(bp);
                uint2 bI = *reinterpret_cast<const uint2*>(bp + PBSZ);
                if (ph2) {
#pragma unroll
                    for (int mt = 0; mt < 2; mt++) {
                        mmaf16(accR[mt][nt], naf[mt][0], naf[mt][1], naf[mt][2], naf[mt][3], bI.x, bI.y);
                        mmaf16(accI[mt][nt], af[mt][0], af[mt][1], af[mt][2], af[mt][3], bR.x, bR.y);
                    }
                } else {
#pragma unroll
                    for (int mt = 0; mt < 2; mt++) {
                        mmaf16(accR[mt][nt], af[mt][0], af[mt][1], af[mt][2], af[mt][3], bR.x, bR.y);
                        mmaf16(accI[mt][nt], af[mt][0], af[mt][1], af[mt][2], af[mt][3], bI.x, bI.y);
                    }
                }
            }
        }
        // issue into buffer (it-1)&3 — its compute finished; protected by this iter's barrier
        if (it + 3 < 64) issue(it + 3);
    }

    // epilogue (mode-dispatched, block-uniform)
#pragma unroll
    for (int mt = 0; mt < 2; mt++) {
#pragma unroll
        for (int hrw = 0; hrw < 2; hrw++) {
            int r = m0 + wm * 32 + mt * 16 + g + hrw * 8;
            int bq = r >> 10, tk = r & 1023;
#pragma unroll
            for (int nt = 0; nt < 4; nt++) {
                int c0 = n0 + wn * 32 + nt * 8 + 2 * t4;
                float vr0 = accR[mt][nt][hrw * 2 + 0] + brp[c0];
                float vr1 = accR[mt][nt][hrw * 2 + 1] + brp[c0 + 1];
                float vi0 = accI[mt][nt][hrw * 2 + 0] + bip[c0];
                float vi1 = accI[mt][nt][hrw * 2 + 1] + bip[c0 + 1];
                int h = c0 >> 6, d = c0 & 63;
                int s = (d & ~15) + slot16(d & 15);

                if (mode == 0) {
                    size_t base = ((size_t)(bq * 16 + h) * 1024 + tk) * 128;
                    *reinterpret_cast<__half2*>(qh + base + s) = __floats2half2_rn(vr0, vr1);
                    *reinterpret_cast<__half2*>(qh + base + 64 + s) = __floats2half2_rn(vi0, vi1);
                } else if (mode == 1) {
                    size_t orow = (size_t)bq * TKV + CACHE + tk;
                    nKr[orow * HIDC + c0] = vr0;  nKr[orow * HIDC + c0 + 1] = vr1;
                    nKi[orow * HIDC + c0] = vi0;  nKi[orow * HIDC + c0 + 1] = vi1;
                    size_t base = ((size_t)(bq * 16 + h) * 4096 + CACHE + tk) * 128;
                    *reinterpret_cast<__half2*>(kh + base + s) = __floats2half2_rn(vr0, vr1);
                    *reinterpret_cast<__half2*>(kh + base + 64 + s) = __floats2half2_rn(vi0, vi1);
                } else {
                    size_t orow = (size_t)bq * TKV + CACHE + tk;
                    nVr[orow * HIDC + c0] = vr0;  nVr[orow * HIDC + c0 + 1] = vr1;
                    nVi[orow * HIDC + c0] = vi0;  nVi[orow * HIDC + c0 + 1] = vi1;
                }
            }
        }
    }
}

// ---------------- O projection (fp32 out + residual, 4-stage) ----------------
__global__ void __launch_bounds__(256, 2)
oproj_kernel(const __half* __restrict__ A1, const __half* __restrict__ A2,
             const __half* __restrict__ Wr, const __half* __restrict__ Wi,
             const float* __restrict__ brp, const float* __restrict__ bip,
             float* __restrict__ Or, float* __restrict__ Oi,
             const float* __restrict__ Rr, const float* __restrict__ Ri) {
    extern __shared__ __half sm[];
    unsigned sbase = (unsigned)__cvta_generic_to_shared(sm);

    int tid = threadIdx.x, lane = tid & 31, wid = tid >> 5;
    int wm = wid & 3, wn = wid >> 2;
    int g = lane >> 2, t4 = lane & 3;
    int n0 = blockIdx.x * 64;
    int m0 = blockIdx.y * 128;

    float accR[2][4][4];
    float accI[2][4][4];
#pragma unroll
    for (int a = 0; a < 2; a++)
#pragma unroll
        for (int b = 0; b < 4; b++)
#pragma unroll
            for (int c = 0; c < 4; c++) { accR[a][b][c] = 0.f; accI[a][b][c] = 0.f; }

    auto issue = [&](int it) {
        bool ph2 = it >= 32;
        int ko = it * 32 - (ph2 ? 1024 : 0);
        const __half* Ap = ph2 ? A2 : A1;
        unsigned stg = (unsigned)(it & 3) * STG_H;
#pragma unroll
        for (int i = 0; i < 2; i++) {
            int id = tid + i * 256;
            int r = id >> 2, c = id & 3;
            cpa16(sbase + (stg + (unsigned)(r * PA_S)) * 2u + c * 16,
                  Ap + (size_t)(m0 + r) * HIDC + ko + c * 8);
        }
#pragma unroll
        for (int i = 0; i < 2; i++) {
            int id = tid + i * 256;
            int pl = id >> 8, r = (id >> 2) & 63, c = id & 3;
            const __half* Wp = pl ? Wi : Wr;
            unsigned off = stg + PASZ + (unsigned)pl * PBSZ;
            cpa16(sbase + (off + (unsigned)(r * PA_S)) * 2u + c * 16,
                  Wp + (size_t)(n0 + r) * HIDC + ko + c * 8);
        }
        cpcommit();
    };

    issue(0);
    issue(1);
    issue(2);

    for (int it = 0; it < 64; it++) {
        if (it < 62) cpwait2(); else if (it == 62) cpwait1(); else cpwait0();
        __syncthreads();

        bool ph2 = (it >= 32);
        const __half* Ab = sm + (it & 3) * STG_H;
        const __half* Bb = Ab + PASZ;

#pragma unroll
        for (int ks = 0; ks < 2; ks++) {
            unsigned af[2][4];
#pragma unroll
            for (int mt = 0; mt < 2; mt++) {
                const __half* ap = Ab + (wm * 32 + mt * 16 + g) * PA_S + ks * 16 + t4 * 4;
                uint2 lo = *reinterpret_cast<const uint2*>(ap);
                uint2 hi = *reinterpret_cast<const uint2*>(ap + 8 * PA_S);
                af[mt][0] = lo.x; af[mt][1] = hi.x; af[mt][2] = lo.y; af[mt][3] = hi.y;
            }
            unsigned naf[2][4];
            if (ph2) {
#pragma unroll
                for (int mt = 0; mt < 2; mt++)
#pragma unroll
                    for (int q = 0; q < 4; q++) naf[mt][q] = af[mt][q] ^ 0x80008000u;
            }
#pragma unroll
            for (int nt = 0; nt < 4; nt++) {
                const __half* bp = Bb + (wn * 32 + nt * 8 + g) * PA_S + ks * 16 + t4 * 4;
                uint2 bR = *reinterpret_cast<const uint2*>(bp);
                uint2 bI = *reinterpret_cast<const uint2*>(bp + PBSZ);
                if (ph2) {
#pragma unroll
                    for (int mt = 0; mt < 2; mt++) {
                        mmaf16(accR[mt][nt], naf[mt][0], naf[mt][1], naf[mt][2], naf[mt][3], bI.x, bI.y);
                        mmaf16(accI[mt][nt], af[mt][0], af[mt][1], af[mt][2], af[mt][3], bR.x, bR.y);
                    }
                } else {
#pragma unroll
                    for (int mt = 0; mt < 2; mt++) {
                        mmaf16(accR[mt][nt], af[mt][0], af[mt][1], af[mt][2], af[mt][3], bR.x, bR.y);
                        mmaf16(accI[mt][nt], af[mt][0], af[mt][1], af[mt][2], af[mt][3], bI.x, bI.y);
                    }
                }
            }
        }
        if (it + 3 < 64) issue(it + 3);
    }

#pragma unroll
    for (int mt = 0; mt < 2; mt++) {
#pragma unroll
        for (int hrw = 0; hrw < 2; hrw++) {
            int r = m0 + wm * 32 + mt * 16 + g + hrw * 8;
#pragma unroll
            for (int nt = 0; nt < 4; nt++) {
                int c0 = n0 + wn * 32 + nt * 8 + 2 * t4;
                float vr0 = accR[mt][nt][hrw * 2 + 0] + brp[c0];
                float vr1 = accR[mt][nt][hrw * 2 + 1] + brp[c0 + 1];
                float vi0 = accI[mt][nt][hrw * 2 + 0] + bip[c0];
                float vi1 = accI[mt][nt][hrw * 2 + 1] + bip[c0 + 1];
                size_t rowo = (size_t)r * HIDC;
                Or[rowo + c0]     = vr0 + Rr[rowo + c0];
                Or[rowo + c0 + 1] = vr1 + Rr[rowo + c0 + 1];
                Oi[rowo + c0]     = vi0 + Ri[rowo + c0];
                Oi[rowo + c0 + 1] = vi1 + Ri[rowo + c0 + 1];
            }
        }
    }
}

// ---------------- Flash attention (fp16 mma, occ 1, balanced pairs — R11) ----------------
constexpr int AQ_S = 136;                 // halves
constexpr int AK_S = 136;
constexpr int AV_S = 72;                  // V^T rows (64 kv + 8 pad)
constexpr int Q_SZ = 128 * AQ_S;          // 17408 halves
constexpr int K_SZ = 64 * AK_S;           // 8704
constexpr int V_SZ = 128 * AV_S;          // 9216
constexpr int AT_SMEM = (Q_SZ + 2 * K_SZ + 2 * V_SZ) * 2;   // 106496 bytes

__global__ void __launch_bounds__(256, 1)
attn_kernel(const __half* __restrict__ Qp, const __half* __restrict__ Kp,
            const __half* __restrict__ Vp,
            __half* __restrict__ ar, __half* __restrict__ ai) {
    extern __shared__ __half smh[];
    __half* Qs = smh;
    unsigned sbase = (unsigned)__cvta_generic_to_shared(smh);

    int tid = threadIdx.x, lane = tid & 31, wid = tid >> 5;
    int g = lane >> 2, t4 = lane & 3;
    int bh = blockIdx.x >> 2;
    int p  = blockIdx.x & 3;
    int b = bh >> 4, h = bh & 15;
    int wq = wid * 16;

    for (int rep = 0; rep < 2; rep++) {
        int qb = rep ? (7 - p) : p;
        int q0 = qb * 128;
        int t_end = min(TKV, q0 + 3200);
        int nIter = t_end / 64;

#pragma unroll
        for (int i = 0; i < 8; i++) {
            int id = tid + i * 256;
            int r = id >> 4, c = id & 15;
            cpa16(sbase + (unsigned)(r * AQ_S) * 2u + c * 16,
                  Qp + ((size_t)bh * 1024 + q0 + r) * 128 + c * 8);
        }

        auto issueKV = [&](int it) {
            int t0 = it * 64;
            int buf = it & 1;
            unsigned kb0 = (unsigned)(Q_SZ + buf * K_SZ) * 2u;
            unsigned vb0 = (unsigned)(Q_SZ + 2 * K_SZ + buf * V_SZ) * 2u;
#pragma unroll
            for (int i = 0; i < 4; i++) {
                int id = tid + i * 256;
                int r = id >> 4, c = id & 15;
                cpa16(kb0 + sbase + (unsigned)(r * AK_S) * 2u + c * 16,
                      Kp + ((size_t)bh * 4096 + t0 + r) * 128 + c * 8);
            }
#pragma unroll
            for (int i = 0; i < 4; i++) {
                int id = tid + i * 256;
                int r = id >> 3, c = id & 7;
                cpa16(vb0 + sbase + (unsigned)(r * AV_S) * 2u + c * 16,
                      Vp + ((size_t)bh * 128 + r) * 4096 + t0 + c * 8);
            }
            cpcommit();
        };

        issueKV(0);
        issueKV(1);

        float mrow[2] = { -1e30f, -1e30f };
        float lrow[2] = { 0.f, 0.f };
        float o[16][4];
#pragma unroll
        for (int nt = 0; nt < 16; nt++) { o[nt][0] = o[nt][1] = o[nt][2] = o[nt][3] = 0.f; }

        for (int it = 0; it < nIter; it++) {
            if (it + 1 < nIter) cpwait1(); else cpwait0();
            __syncthreads();

            int t0 = it * 64;
            int buf = it & 1;
            const __half* Kb = smh + Q_SZ + buf * K_SZ;
            const __half* Vb = smh + Q_SZ + 2 * K_SZ + buf * V_SZ;

            float s[8][4];
#pragma unroll
            for (int nt = 0; nt < 8; nt++) { s[nt][0] = s[nt][1] = s[nt][2] = s[nt][3] = 0.f; }
#pragma unroll
            for (int ks = 0; ks < 8; ks++) {
                const __half* ap = Qs + (wq + g) * AQ_S + ks * 16 + t4 * 4;
                uint2 lo = *reinterpret_cast<const uint2*>(ap);
                uint2 hi = *reinterpret_cast<const uint2*>(ap + 8 * AQ_S);
                unsigned a0 = lo.x, a1 = hi.x, a2 = lo.y, a3 = hi.y;
#pragma unroll
                for (int nt = 0; nt < 8; nt++) {
                    uint2 bb = *reinterpret_cast<const uint2*>(
                        Kb + (nt * 8 + g) * AK_S + ks * 16 + t4 * 4);
                    mmaf16(s[nt], a0, a1, a2, a3, bb.x, bb.y);
                }
            }

            bool needmask = (t0 + 63 > q0 + CACHE);
            int rg0 = q0 + wq + g, rg1 = rg0 + 8;
#pragma unroll
            for (int nt = 0; nt < 8; nt++) {
                s[nt][0] *= 0.125f; s[nt][1] *= 0.125f; s[nt][2] *= 0.125f; s[nt][3] *= 0.125f;
                if (needmask) {
                    int c0 = t0 + nt * 8 + 2 * t4;
                    if (c0     > rg0 + CACHE) s[nt][0] = -1e30f;
                    if (c0 + 1 > rg0 + CACHE) s[nt][1] = -1e30f;
                    if (c0     > rg1 + CACHE) s[nt][2] = -1e30f;
                    if (c0 + 1 > rg1 + CACHE) s[nt][3] = -1e30f;
                }
            }

            float mx0 = -1e30f, mx1 = -1e30f;
#pragma unroll
            for (int nt = 0; nt < 8; nt++) {
                mx0 = fmaxf(mx0, fmaxf(s[nt][0], s[nt][1]));
                mx1 = fmaxf(mx1, fmaxf(s[nt][2], s[nt][3]));
            }
            mx0 = fmaxf(mx0, __shfl_xor_sync(0xffffffffu, mx0, 1));
            mx0 = fmaxf(mx0, __shfl_xor_sync(0xffffffffu, mx0, 2));
            mx1 = fmaxf(mx1, __shfl_xor_sync(0xffffffffu, mx1, 1));
            mx1 = fmaxf(mx1, __shfl_xor_sync(0xffffffffu, mx1, 2));
            float mn0 = fmaxf(mrow[0], mx0), mn1 = fmaxf(mrow[1], mx1);
            float al0 = __expf(mrow[0] - mn0), al1 = __expf(mrow[1] - mn1);
            float rs0 = 0.f, rs1 = 0.f;
#pragma unroll
            for (int nt = 0; nt < 8; nt++) {
                s[nt][0] = __expf(s[nt][0] - mn0);
                s[nt][1] = __expf(s[nt][1] - mn0);
                s[nt][2] = __expf(s[nt][2] - mn1);
                s[nt][3] = __expf(s[nt][3] - mn1);
                rs0 += s[nt][0] + s[nt][1];
                rs1 += s[nt][2] + s[nt][3];
            }
            rs0 += __shfl_xor_sync(0xffffffffu, rs0, 1);
            rs0 += __shfl_xor_sync(0xffffffffu, rs0, 2);
            rs1 += __shfl_xor_sync(0xffffffffu, rs1, 1);
            rs1 += __shfl_xor_sync(0xffffffffu, rs1, 2);
            lrow[0] = lrow[0] * al0 + rs0;
            lrow[1] = lrow[1] * al1 + rs1;
            mrow[0] = mn0; mrow[1] = mn1;
#pragma unroll
            for (int nt = 0; nt < 16; nt++) {
                o[nt][0] *= al0; o[nt][1] *= al0; o[nt][2] *= al1; o[nt][3] *= al1;
            }

#pragma unroll
            for (int kb = 0; kb < 4; kb++) {
                unsigned a0 = packh2(s[2 * kb][0], s[2 * kb][1]);
                unsigned a1 = packh2(s[2 * kb][2], s[2 * kb][3]);
                unsigned a2 = packh2(s[2 * kb + 1][0], s[2 * kb + 1][1]);
                unsigned a3 = packh2(s[2 * kb + 1][2], s[2 * kb + 1][3]);
#pragma unroll
                for (int nt = 0; nt < 16; nt++) {
                    const __half* vp = Vb + (nt * 8 + g) * AV_S + kb * 16 + 2 * t4;
                    unsigned b0 = *reinterpret_cast<const unsigned*>(vp);
                    unsigned b1 = *reinterpret_cast<const unsigned*>(vp + 8);
                    mmaf16(o[nt], a0, a1, a2, a3, b0, b1);
                }
            }
            __syncthreads();
            if (it + 2 < nIter) issueKV(it + 2);
        }

        // epilogue — fp16 perm16 planes for the O-projection
        float il0 = 1.0f / lrow[0], il1 = 1.0f / lrow[1];
        int r0 = q0 + wq + g;
        size_t rb0 = (size_t)(b * SEQ + r0) * HIDC;
        size_t rb1 = rb0 + (size_t)8 * HIDC;
#pragma unroll
        for (int nt = 0; nt < 16; nt++) {
            int d0 = nt * 8 + 2 * t4;
            __half* dst = (d0 < 64) ? ar : ai;
            int dd = d0 & 63;
            int hid = h * 64 + dd;
            int s = (hid & ~15) + slot16(hid & 15);
            *reinterpret_cast<__half2*>(dst + rb0 + s) =
                __floats2half2_rn(o[nt][0] * il0, o[nt][1] * il0);
            *reinterpret_cast<__half2*>(dst + rb1 + s) =
                __floats2half2_rn(o[nt][2] * il1, o[nt][3] * il1);
        }
    }
}

// ---------------- launcher (forked-stream schedule) ----------------
extern "C" void kernel_launch(void* const* d_in, const int* in_sizes, int n_in,
                              void* d_out, int out_size) {
    const float* hr    = (const float*)d_in[0];
    const float* hi    = (const float*)d_in[1];
    const float* Kcr   = (const float*)d_in[2];
    const float* Kci   = (const float*)d_in[3];
    const float* Vcr   = (const float*)d_in[4];
    const float* Vci   = (const float*)d_in[5];
    const float* gamma = (const float*)d_in[6];
    const float* betar = (const float*)d_in[7];
    const float* betai = (const float*)d_in[8];
    const float* qbr = (const float*)d_in[11], *qbi = (const float*)d_in[12];
    const float* kbr = (const float*)d_in[15], *kbi = (const float*)d_in[16];
    const float* vbr = (const float*)d_in[19], *vbi = (const float*)d_in[20];
    const float* obr = (const float*)d_in[23], *obi = (const float*)d_in[24];

    float* out = (float*)d_out;
    float* outR = out + OFF_OUT_RE;
    float* outI = out + OFF_OUT_IM;
    float* nKr  = out + OFF_K_RE;
    float* nKi  = out + OFF_K_IM;
    float* nVr  = out + OFF_V_RE;
    float* nVi  = out + OFF_V_IM;

    __half *nrh, *nih, *arh, *aih, *qh, *kh, *vt, *wh;
    cudaGetSymbolAddress((void**)&nrh, g_nrh);
    cudaGetSymbolAddress((void**)&nih, g_nih);
    cudaGetSymbolAddress((void**)&arh, g_arh);
    cudaGetSymbolAddress((void**)&aih, g_aih);
    cudaGetSymbolAddress((void**)&qh, g_qh);
    cudaGetSymbolAddress((void**)&kh, g_kh);
    cudaGetSymbolAddress((void**)&vt, g_vt);
    cudaGetSymbolAddress((void**)&wh, g_wh);

    cudaFuncSetAttribute(attn_kernel, cudaFuncAttributeMaxDynamicSharedMemorySize, AT_SMEM);
    cudaFuncSetAttribute(qkv_kernel, cudaFuncAttributeMaxDynamicSharedMemorySize, PJ_SMEM);
    cudaFuncSetAttribute(oproj_kernel, cudaFuncAttributeMaxDynamicSharedMemorySize, PJ_SMEM);

    // one-time stream/event setup (first call is the uncaptured correctness run)
    static cudaStream_t sB = nullptr, sC = nullptr;
    static cudaEvent_t e0 = nullptr, eB = nullptr, eC = nullptr;
    if (!sB) {
        cudaStreamCreateWithFlags(&sB, cudaStreamNonBlocking);
        cudaStreamCreateWithFlags(&sC, cudaStreamNonBlocking);
        cudaEventCreateWithFlags(&e0, cudaEventDisableTiming);
        cudaEventCreateWithFlags(&eB, cudaEventDisableTiming);
        cudaEventCreateWithFlags(&eC, cudaEventDisableTiming);
    }

    // fork point
    cudaEventRecord(e0, 0);

    // stream B: weight convert (independent of LN)
    cudaStreamWaitEvent(sB, e0, 0);
    wconv_kernel<<<(int)((8u * 1024 * 1024) / 256), 256, 0, sB>>>(
        (const float*)d_in[9],  (const float*)d_in[10],
        (const float*)d_in[13], (const float*)d_in[14],
        (const float*)d_in[17], (const float*)d_in[18],
        (const float*)d_in[21], (const float*)d_in[22], wh);
    cudaEventRecord(eB, sB);

    // stream C: fp32 cache copies + K-cache fp16 conversion + V^T cache part
    cudaStreamWaitEvent(sC, e0, 0);
    for (int b = 0; b < NBAT; b++) {
        size_t dofs = (size_t)b * TKV * HIDC;
        size_t sofs = (size_t)b * CACHE * HIDC;
        size_t bytes = (size_t)CACHE * HIDC * sizeof(float);
        cudaMemcpyAsync(nKr + dofs, Kcr + sofs, bytes, cudaMemcpyDeviceToDevice, sC);
        cudaMemcpyAsync(nKi + dofs, Kci + sofs, bytes, cudaMemcpyDeviceToDevice, sC);
        cudaMemcpyAsync(nVr + dofs, Vcr + sofs, bytes, cudaMemcpyDeviceToDevice, sC);
        cudaMemcpyAsync(nVi + dofs, Vci + sofs, bytes, cudaMemcpyDeviceToDevice, sC);
    }
    kcache_conv<<<(int)((2u * 3072 * 1024) / 256), 256, 0, sC>>>(Kcr, Kci, kh);
    // V^T for cache tokens, straight from the input cache (stride 3072)
    vtrans_kernel<<<dim3(48, 32), 256, 0, sC>>>(Vcr, Vci, vt, CACHE, 0, 0);
    cudaEventRecord(eC, sC);

    // main stream: LN (overlaps wconv), then qkv (overlaps stream C)
    ln_kernel<<<MTOT, 256>>>(hr, hi, gamma, betar, betai, nrh, nih);

    cudaStreamWaitEvent(0, eB, 0);
    qkv_kernel<<<dim3(HIDC / 64, MTOT / 128, 3), 256, PJ_SMEM>>>(
        nrh, nih, wh, qbr, qbi, kbr, kbi, vbr, vbi,
        nKr, nKi, nVr, nVi, qh, kh);

    // V^T for new tokens (reads qkv's fp32 V output)
    vtrans_kernel<<<dim3(16, 32), 256>>>(nVr, nVi, vt, TKV, CACHE, CACHE);

    // join memory stream before attention (K fp16 cache plane + V^T cache part)
    cudaStreamWaitEvent(0, eC, 0);
    attn_kernel<<<128, 256, AT_SMEM>>>(qh, kh, vt, arh, aih);

    constexpr size_t WPL = 1024u * 1024u;
    oproj_kernel<<<dim3(HIDC / 64, MTOT / 128), 256, PJ_SMEM>>>(
        arh, aih, wh + 6 * WPL, wh + 7 * WPL, obr, obi, outR, outI, hr, hi);
}